// round 6
// baseline (speedup 1.0000x reference)
#include <cuda_runtime.h>
#include <cstdint>
#include <math.h>

#define B_  2
#define T_  2048
#define E_  1024
#define H_  16
#define D_  64
#define BH_ (B_*H_)       // 32

// ---------------------------------------------------------------------------
// Device scratch
// ---------------------------------------------------------------------------
__device__ float g_q[(size_t)BH_ * T_ * D_];
__device__ float g_k[(size_t)BH_ * T_ * D_];
__device__ float g_v[(size_t)BH_ * T_ * D_];
__device__ float g_m[(size_t)BH_ * T_];       // column max (log2 domain)
__device__ float g_zinv[(size_t)BH_ * T_];    // column 1/sum

// scale * log2(e): softmax computed in base-2 domain
#define KS2 0.18033688011112042592f

// ---------------------------------------------------------------------------
// helpers
// ---------------------------------------------------------------------------
__device__ __forceinline__ uint32_t f2tf(float f) {
    uint32_t u;
    asm("cvt.rna.tf32.f32 %0, %1;" : "=r"(u) : "f"(f));
    return u;
}

// non-volatile: pure data-flow op, lets ptxas pipeline MMA with LDSM
__device__ __forceinline__ void mma8(float* c, const uint32_t* a, const uint32_t* b) {
    asm("mma.sync.aligned.m16n8k8.row.col.f32.tf32.tf32.f32 "
        "{%0,%1,%2,%3},{%4,%5,%6,%7},{%8,%9},{%0,%1,%2,%3};"
        : "+f"(c[0]), "+f"(c[1]), "+f"(c[2]), "+f"(c[3])
        : "r"(a[0]), "r"(a[1]), "r"(a[2]), "r"(a[3]), "r"(b[0]), "r"(b[1]));
}

// A-operand fragment (16 rows x k8) via one ldmatrix.x4. base row-major, S words/row.
__device__ __forceinline__ void ldsmA(uint32_t* r, const uint32_t* base,
                                      int row0, int ko, int lane, int S) {
    const uint32_t* p = base +
        (size_t)(row0 + (lane & 7) + ((lane >> 3) & 1) * 8) * S + ko + (lane >> 4) * 4;
    uint32_t addr = (uint32_t)__cvta_generic_to_shared(p);
    asm volatile("ldmatrix.sync.aligned.m8n8.x4.shared.b16 {%0,%1,%2,%3}, [%4];"
                 : "=r"(r[0]), "=r"(r[1]), "=r"(r[2]), "=r"(r[3]) : "r"(addr));
}

// Two B-operand fragments (cols n0..n0+15 x k8) via one ldmatrix.x4.
__device__ __forceinline__ void ldsmB2(uint32_t* r, const uint32_t* base,
                                       int n0, int ko, int lane, int S) {
    const uint32_t* p = base +
        (size_t)(n0 + ((lane >> 4) << 3) + (lane & 7)) * S + ko + ((lane >> 3) & 1) * 4;
    uint32_t addr = (uint32_t)__cvta_generic_to_shared(p);
    asm volatile("ldmatrix.sync.aligned.m8n8.x4.shared.b16 {%0,%1,%2,%3}, [%4];"
                 : "=r"(r[0]), "=r"(r[1]), "=r"(r[2]), "=r"(r[3]) : "r"(addr));
}

// fast 2^y for y <= 0, FMA-pipe only. rel err ~2.4e-6.
__device__ __forceinline__ float fexp2(float y) {
    y = fmaxf(y, -120.f);
    float t = y + 12582912.f;
    int   iy = __float_as_int(t);
    float fl = t - 12582912.f;
    float f  = y - fl;
    float p = 0.0013333558f;
    p = fmaf(p, f, 0.0096181291f);
    p = fmaf(p, f, 0.0555041087f);
    p = fmaf(p, f, 0.2402265069f);
    p = fmaf(p, f, 0.6931471806f);
    p = fmaf(p, f, 1.0f);
    return __int_as_float(__float_as_int(p) + (iy << 23));
}

// ---------------------------------------------------------------------------
// Kernel 1: fused QKV projection, 2 heads per block.
// Block 128(M) x 128(N = 2 heads x 64), 8 warps of 64x32, K-tile 32.
// 256 threads, 2 CTAs/SM target.
// ---------------------------------------------------------------------------
__global__ __launch_bounds__(256, 2) void proj_kernel(const float* __restrict__ X,
                                                      const float* __restrict__ qw,
                                                      const float* __restrict__ kw,
                                                      const float* __restrict__ vw,
                                                      const float* __restrict__ qb,
                                                      const float* __restrict__ kb,
                                                      const float* __restrict__ vb,
                                                      float* __restrict__ oq,
                                                      float* __restrict__ ok,
                                                      float* __restrict__ ov)
{
    const float* W; const float* bias; float* out;
    if (blockIdx.z == 0)      { W = qw; bias = qb; out = oq; }
    else if (blockIdx.z == 1) { W = kw; bias = kb; out = ok; }
    else                      { W = vw; bias = vb; out = ov; }

    __shared__ __align__(16) uint32_t As[128][36];   // [m][k]
    __shared__ __align__(16) uint32_t Bs[128][36];   // [n][k] (n = 2 heads x 64 d)

    const int m0   = blockIdx.x * 128;
    const int h0   = blockIdx.y * 2;
    const int tid  = threadIdx.x;
    const int lane = tid & 31;
    const int warp = tid >> 5;
    const int wm   = warp >> 2;     // 0..1 (64 rows)
    const int wn   = warp & 3;      // 0..3 (32 cols)
    const int g    = lane >> 2;
    const int tg   = lane & 3;

    float acc[4][4][4] = {};

    for (int k0 = 0; k0 < E_; k0 += 32) {
        // A fill: 128 rows x 32 k = 1024 float4, 4 per thread
        #pragma unroll
        for (int j = 0; j < 4; j++) {
            int q = tid + j * 256;
            int row = q >> 3, c = (q & 7) * 4;
            float4 v = *reinterpret_cast<const float4*>(
                X + (size_t)(m0 + row) * E_ + k0 + c);
            uint4 u;
            u.x = f2tf(v.x); u.y = f2tf(v.y); u.z = f2tf(v.z); u.w = f2tf(v.w);
            *reinterpret_cast<uint4*>(&As[row][c]) = u;
        }
        // B fill: W[h][e][d] -> Bs[n][e]
        #pragma unroll
        for (int j = 0; j < 4; j++) {
            int q  = tid + j * 256;
            int n  = (q >> 5) * 4;
            int e  = q & 31;
            int h  = h0 + (n >> 6);
            int d  = n & 63;
            float4 v = *reinterpret_cast<const float4*>(
                W + ((size_t)h * E_ + k0 + e) * D_ + d);
            Bs[n + 0][e] = f2tf(v.x);
            Bs[n + 1][e] = f2tf(v.y);
            Bs[n + 2][e] = f2tf(v.z);
            Bs[n + 3][e] = f2tf(v.w);
        }
        __syncthreads();

        #pragma unroll
        for (int ks = 0; ks < 4; ks++) {
            uint32_t a[4][4], b[8];
            #pragma unroll
            for (int mf = 0; mf < 4; mf++)
                ldsmA(a[mf], &As[0][0], wm * 64 + mf * 16, ks * 8, lane, 36);
            ldsmB2(&b[0], &Bs[0][0], wn * 32 + 0,  ks * 8, lane, 36);
            ldsmB2(&b[4], &Bs[0][0], wn * 32 + 16, ks * 8, lane, 36);
            #pragma unroll
            for (int mf = 0; mf < 4; mf++)
                #pragma unroll
                for (int nf = 0; nf < 4; nf++)
                    mma8(acc[mf][nf], a[mf], &b[nf * 2]);
        }
        __syncthreads();
    }

    // epilogue: out (B,H,T,D) + bias
    #pragma unroll
    for (int mf = 0; mf < 4; mf++) {
        #pragma unroll
        for (int half = 0; half < 2; half++) {
            int m  = m0 + wm * 64 + mf * 16 + g + half * 8;
            int bb = m >> 11;
            int t  = m & (T_ - 1);
            #pragma unroll
            for (int nf = 0; nf < 4; nf++) {
                int nn = wn * 32 + nf * 8 + 2 * tg;
                int h  = h0 + (nn >> 6);
                int d  = nn & 63;
                float2 val;
                val.x = acc[mf][nf][half * 2 + 0] + bias[h * D_ + d];
                val.y = acc[mf][nf][half * 2 + 1] + bias[h * D_ + d + 1];
                *reinterpret_cast<float2*>(
                    out + (((size_t)bb * H_ + h) * T_ + t) * D_ + d) = val;
            }
        }
    }
}

// ---------------------------------------------------------------------------
// Pass A: column softmax stats (log2 domain), S never materialized.
// grid (s_tile=16, bh=32), block 256, 8 warps of 64t x 32s.
// ---------------------------------------------------------------------------
__global__ __launch_bounds__(256) void stats_kernel(const float* __restrict__ Q,
                                                    const float* __restrict__ K,
                                                    float* __restrict__ m_out,
                                                    float* __restrict__ z_out)
{
    extern __shared__ __align__(16) char smem_raw[];
    uint32_t* Ks = reinterpret_cast<uint32_t*>(smem_raw);                 // [128][68]
    uint32_t* Qs = Ks + 128 * 68;                                         // [128][68]
    float* redm = reinterpret_cast<float*>(Qs + 128 * 68);                // [2][128]
    float* redz = redm + 256;                                             // [2][128]
    float* mrun = redz + 256;                                             // [128]
    float* zrun = mrun + 128;                                             // [128]

    const int st   = blockIdx.x;
    const int bh   = blockIdx.y;
    const int tid  = threadIdx.x;
    const int lane = tid & 31;
    const int warp = tid >> 5;
    const int wm   = warp >> 2;
    const int wn   = warp & 3;
    const int g    = lane >> 2;
    const int tg   = lane & 3;

    const float* Kp = K + ((size_t)bh * T_ + st * 128) * D_;
    #pragma unroll
    for (int j = 0; j < 8; j++) {
        int q = tid + j * 256;
        int row = q >> 4, c = (q & 15) * 4;
        float4 v = *reinterpret_cast<const float4*>(Kp + (size_t)row * D_ + c);
        uint4 u;
        u.x = f2tf(v.x); u.y = f2tf(v.y); u.z = f2tf(v.z); u.w = f2tf(v.w);
        *reinterpret_cast<uint4*>(Ks + row * 68 + c) = u;
    }
    if (tid < 128) { mrun[tid] = -3.0e38f; zrun[tid] = 0.f; }
    __syncthreads();

    for (int it = st; it < T_ / 128; it++) {
        const float* Qp = Q + ((size_t)bh * T_ + it * 128) * D_;
        #pragma unroll
        for (int j = 0; j < 8; j++) {
            int q = tid + j * 256;
            int row = q >> 4, c = (q & 15) * 4;
            float4 v = *reinterpret_cast<const float4*>(Qp + (size_t)row * D_ + c);
            uint4 u;
            u.x = f2tf(v.x); u.y = f2tf(v.y); u.z = f2tf(v.z); u.w = f2tf(v.w);
            *reinterpret_cast<uint4*>(Qs + row * 68 + c) = u;
        }
        __syncthreads();

        float acc[4][4][4] = {};
        #pragma unroll
        for (int ks = 0; ks < 8; ks++) {
            uint32_t a[4][4], b[8];
            #pragma unroll
            for (int mf = 0; mf < 4; mf++)
                ldsmA(a[mf], Qs, wm * 64 + mf * 16, ks * 8, lane, 68);
            ldsmB2(&b[0], Ks, wn * 32 + 0,  ks * 8, lane, 68);
            ldsmB2(&b[4], Ks, wn * 32 + 16, ks * 8, lane, 68);
            #pragma unroll
            for (int mf = 0; mf < 4; mf++)
                #pragma unroll
                for (int nf = 0; nf < 4; nf++)
                    mma8(acc[mf][nf], a[mf], &b[nf * 2]);
        }

        // scale to log2 domain + causal mask (diag tile only)
        if (it == st) {
            #pragma unroll
            for (int mf = 0; mf < 4; mf++)
                #pragma unroll
                for (int hh = 0; hh < 2; hh++) {
                    int tl = wm * 64 + mf * 16 + g + hh * 8;
                    #pragma unroll
                    for (int nf = 0; nf < 4; nf++)
                        #pragma unroll
                        for (int ci = 0; ci < 2; ci++) {
                            int sl = wn * 32 + nf * 8 + 2 * tg + ci;
                            float x = acc[mf][nf][hh * 2 + ci] * KS2;
                            acc[mf][nf][hh * 2 + ci] = (tl >= sl) ? x : -3.0e38f;
                        }
                }
        } else {
            #pragma unroll
            for (int mf = 0; mf < 4; mf++)
                #pragma unroll
                for (int nf = 0; nf < 4; nf++)
                    #pragma unroll
                    for (int c = 0; c < 4; c++)
                        acc[mf][nf][c] *= KS2;
        }

        // per-warp column max
        #pragma unroll
        for (int nf = 0; nf < 4; nf++)
            #pragma unroll
            for (int ci = 0; ci < 2; ci++) {
                float v = -3.0e38f;
                #pragma unroll
                for (int mf = 0; mf < 4; mf++) {
                    v = fmaxf(v, acc[mf][nf][ci]);
                    v = fmaxf(v, acc[mf][nf][2 + ci]);
                }
                v = fmaxf(v, __shfl_xor_sync(0xffffffffu, v, 4));
                v = fmaxf(v, __shfl_xor_sync(0xffffffffu, v, 8));
                v = fmaxf(v, __shfl_xor_sync(0xffffffffu, v, 16));
                if (lane < 4) redm[wm * 128 + wn * 32 + nf * 8 + 2 * tg + ci] = v;
            }
        __syncthreads();

        // exp2-sum with combined tile max
        #pragma unroll
        for (int nf = 0; nf < 4; nf++)
            #pragma unroll
            for (int ci = 0; ci < 2; ci++) {
                int col = wn * 32 + nf * 8 + 2 * tg + ci;
                float mt = fmaxf(redm[col], redm[128 + col]);
                float zs = 0.f;
                #pragma unroll
                for (int mf = 0; mf < 4; mf++) {
                    zs += fexp2(acc[mf][nf][ci] - mt);
                    zs += fexp2(acc[mf][nf][2 + ci] - mt);
                }
                zs += __shfl_xor_sync(0xffffffffu, zs, 4);
                zs += __shfl_xor_sync(0xffffffffu, zs, 8);
                zs += __shfl_xor_sync(0xffffffffu, zs, 16);
                if (lane < 4) redz[wm * 128 + col] = zs;
            }
        __syncthreads();

        if (tid < 128) {
            float mt = fmaxf(redm[tid], redm[128 + tid]);
            float zt = redz[tid] + redz[128 + tid];
            float mo = mrun[tid];
            float mn = fmaxf(mo, mt);
            zrun[tid] = zrun[tid] * fexp2(mo - mn) + zt * fexp2(mt - mn);
            mrun[tid] = mn;
        }
        __syncthreads();
    }

    if (tid < 128) {
        int s = st * 128 + tid;
        m_out[bh * T_ + s] = mrun[tid];
        z_out[bh * T_ + s] = 1.0f / zrun[tid];
    }
}

// ---------------------------------------------------------------------------
// Pass B: out = P @ (V * zinv), P recomputed in log2 domain.
// grid (t_tile=16 reversed, bh=32), block 256.
// QK warp tile 64t x 16s; PV warp tile 32t x 32d.
// ---------------------------------------------------------------------------
__global__ __launch_bounds__(256) void out_kernel(const float* __restrict__ Q,
                                                  const float* __restrict__ K,
                                                  const float* __restrict__ V,
                                                  const float* __restrict__ mcol_g,
                                                  const float* __restrict__ zcol_g,
                                                  float* __restrict__ out)
{
    extern __shared__ __align__(16) char smem_raw[];
    uint32_t* Qs = reinterpret_cast<uint32_t*>(smem_raw);  // [128][68]
    uint32_t* Ps = Qs + 128 * 68;                          // [128][68]
    uint32_t* Ks = Ps + 128 * 68;                          // [64][68]
    uint32_t* Vs = Ks + 64 * 68;                           // [64][68]
    float* mcol  = reinterpret_cast<float*>(Vs + 64 * 68); // [64]
    float* zcol  = mcol + 64;                              // [64]

    const int tt   = (T_ / 128 - 1) - blockIdx.x;
    const int bh   = blockIdx.y;
    const int bb   = bh >> 4;
    const int h    = bh & 15;
    const int tid  = threadIdx.x;
    const int lane = tid & 31;
    const int warp = tid >> 5;
    const int g    = lane >> 2;
    const int tg   = lane & 3;

    const int wq_m = warp >> 2, wq_n = warp & 3;
    const int wp_m = warp & 3,  wp_n = warp >> 2;

    const int t0 = tt * 128;

    const float* Qp = Q + ((size_t)bh * T_ + t0) * D_;
    #pragma unroll
    for (int j = 0; j < 8; j++) {
        int q = tid + j * 256;
        int row = q >> 4, c = (q & 15) * 4;
        float4 v = *reinterpret_cast<const float4*>(Qp + (size_t)row * D_ + c);
        uint4 u;
        u.x = f2tf(v.x); u.y = f2tf(v.y); u.z = f2tf(v.z); u.w = f2tf(v.w);
        *reinterpret_cast<uint4*>(Qs + row * 68 + c) = u;
    }

    float oacc[2][4][4] = {};

    for (int s0 = 0; s0 <= t0 + 64; s0 += 64) {
        __syncthreads();

        const float* Kp = K + ((size_t)bh * T_ + s0) * D_;
        const float* Vp = V + ((size_t)bh * T_ + s0) * D_;
        #pragma unroll
        for (int j = 0; j < 4; j++) {
            int q = tid + j * 256;
            int row = q >> 4, c = (q & 15) * 4;
            float4 kv = *reinterpret_cast<const float4*>(Kp + (size_t)row * D_ + c);
            uint4 uk;
            uk.x = f2tf(kv.x); uk.y = f2tf(kv.y); uk.z = f2tf(kv.z); uk.w = f2tf(kv.w);
            *reinterpret_cast<uint4*>(Ks + row * 68 + c) = uk;
            float4 vv = *reinterpret_cast<const float4*>(Vp + (size_t)row * D_ + c);
            uint4 uv;
            uv.x = f2tf(vv.x); uv.y = f2tf(vv.y); uv.z = f2tf(vv.z); uv.w = f2tf(vv.w);
            *reinterpret_cast<uint4*>(Vs + row * 68 + c) = uv;
        }
        if (tid < 64) {
            mcol[tid] = mcol_g[bh * T_ + s0 + tid];
            zcol[tid] = zcol_g[bh * T_ + s0 + tid];
        }
        __syncthreads();

        // QK chunk: 128t x 64s
        float sacc[4][2][4] = {};
        #pragma unroll
        for (int ks = 0; ks < 8; ks++) {
            uint32_t a[4][4], b[4];
            #pragma unroll
            for (int mf = 0; mf < 4; mf++)
                ldsmA(a[mf], Qs, wq_m * 64 + mf * 16, ks * 8, lane, 68);
            ldsmB2(&b[0], Ks, wq_n * 16, ks * 8, lane, 68);
            #pragma unroll
            for (int mf = 0; mf < 4; mf++)
                #pragma unroll
                for (int nf = 0; nf < 2; nf++)
                    mma8(sacc[mf][nf], a[mf], &b[nf * 2]);
        }

        // exp2 + normalize + stage P (tf32)
        const bool needmask = (s0 + 63 > t0);
        #pragma unroll
        for (int mf = 0; mf < 4; mf++)
            #pragma unroll
            for (int hh = 0; hh < 2; hh++) {
                int tl = wq_m * 64 + mf * 16 + g + hh * 8;
                #pragma unroll
                for (int nf = 0; nf < 2; nf++)
                    #pragma unroll
                    for (int ci = 0; ci < 2; ci++) {
                        int sl = wq_n * 16 + nf * 8 + 2 * tg + ci;
                        float y = fmaf(sacc[mf][nf][hh * 2 + ci], KS2, -mcol[sl]);
                        float p = fexp2(y) * zcol[sl];
                        if (needmask && (s0 + sl > t0 + tl)) p = 0.f;
                        Ps[tl * 68 + sl] = f2tf(p);
                    }
            }
        __syncthreads();

        // PV: 128t x 64d over k=64
        #pragma unroll
        for (int ks = 0; ks < 8; ks++) {
            uint32_t a[2][4], b[4][2];
            #pragma unroll
            for (int mf = 0; mf < 2; mf++)
                ldsmA(a[mf], Ps, wp_m * 32 + mf * 16, ks * 8, lane, 68);
            #pragma unroll
            for (int nf = 0; nf < 4; nf++) {
                int cn = wp_n * 32 + nf * 8 + g;
                b[nf][0] = Vs[(ks * 8 + tg) * 68 + cn];
                b[nf][1] = Vs[(ks * 8 + tg + 4) * 68 + cn];
            }
            #pragma unroll
            for (int mf = 0; mf < 2; mf++)
                #pragma unroll
                for (int nf = 0; nf < 4; nf++)
                    mma8(oacc[mf][nf], a[mf], b[nf]);
        }
    }

    // epilogue: (B,T,H,D) head-major concat
    #pragma unroll
    for (int mf = 0; mf < 2; mf++)
        #pragma unroll
        for (int hh = 0; hh < 2; hh++) {
            int t = t0 + wp_m * 32 + mf * 16 + g + hh * 8;
            #pragma unroll
            for (int nf = 0; nf < 4; nf++) {
                int d = wp_n * 32 + nf * 8 + 2 * tg;
                float2 val;
                val.x = oacc[mf][nf][hh * 2 + 0];
                val.y = oacc[mf][nf][hh * 2 + 1];
                *reinterpret_cast<float2*>(
                    out + (((size_t)bb * T_ + t) * H_ + h) * D_ + d) = val;
            }
        }
}

// ---------------------------------------------------------------------------
// Launch
// ---------------------------------------------------------------------------
extern "C" void kernel_launch(void* const* d_in, const int* in_sizes, int n_in,
                              void* d_out, int out_size)
{
    const float* X   = (const float*)d_in[0];
    const float* k_w = (const float*)d_in[1];
    const float* k_b = (const float*)d_in[2];
    const float* q_w = (const float*)d_in[3];
    const float* q_b = (const float*)d_in[4];
    const float* v_w = (const float*)d_in[5];
    const float* v_b = (const float*)d_in[6];
    float* out = (float*)d_out;

    float *pq, *pk, *pv, *pm, *pz;
    cudaGetSymbolAddress((void**)&pq, g_q);
    cudaGetSymbolAddress((void**)&pk, g_k);
    cudaGetSymbolAddress((void**)&pv, g_v);
    cudaGetSymbolAddress((void**)&pm, g_m);
    cudaGetSymbolAddress((void**)&pz, g_zinv);

    const int SA = (2 * 128 * 68) * 4 + (256 + 256 + 128 + 128) * 4;        // 72704
    const int SB = (128 * 68 + 128 * 68 + 64 * 68 + 64 * 68) * 4 + 128 * 4; // 104960

    cudaFuncSetAttribute(stats_kernel, cudaFuncAttributeMaxDynamicSharedMemorySize, SA);
    cudaFuncSetAttribute(out_kernel,   cudaFuncAttributeMaxDynamicSharedMemorySize, SB);

    dim3 projGrid(B_ * T_ / 128, H_ / 2, 3);   // (32, 8, 3)
    proj_kernel<<<projGrid, 256>>>(X, q_w, k_w, v_w, q_b, k_b, v_b, pq, pk, pv);

    dim3 stGrid(T_ / 128, BH_);
    stats_kernel<<<stGrid, 256, SA>>>(pq, pk, pm, pz);

    dim3 outGrid(T_ / 128, BH_);
    out_kernel<<<outGrid, 256, SB>>>(pq, pk, pv, pm, pz, out);
}

// round 8
// speedup vs baseline: 1.0556x; 1.0556x over previous
#include <cuda_runtime.h>
#include <cstdint>
#include <math.h>

#define B_  2
#define T_  2048
#define E_  1024
#define H_  16
#define D_  64
#define BH_ (B_*H_)       // 32

// ---------------------------------------------------------------------------
// Device scratch
// ---------------------------------------------------------------------------
__device__ float g_q[(size_t)BH_ * T_ * D_];
__device__ float g_k[(size_t)BH_ * T_ * D_];
__device__ float g_v[(size_t)BH_ * T_ * D_];
__device__ float g_cs[(size_t)BH_ * T_];      // column factor exp2(-m)/z

// scale * log2(e): softmax computed in base-2 domain
#define KS2 0.18033688011112042592f

// ---------------------------------------------------------------------------
// helpers
// ---------------------------------------------------------------------------
__device__ __forceinline__ float fex2(float x) {
    float r;
    asm("ex2.approx.f32 %0, %1;" : "=f"(r) : "f"(x));
    return r;
}

__device__ __forceinline__ uint32_t f2tf(float f) {
    uint32_t u;
    asm("cvt.rna.tf32.f32 %0, %1;" : "=r"(u) : "f"(f));
    return u;
}

// non-volatile: pure data-flow op, lets ptxas pipeline MMA with LDSM
__device__ __forceinline__ void mma8(float* c, const uint32_t* a, const uint32_t* b) {
    asm("mma.sync.aligned.m16n8k8.row.col.f32.tf32.tf32.f32 "
        "{%0,%1,%2,%3},{%4,%5,%6,%7},{%8,%9},{%0,%1,%2,%3};"
        : "+f"(c[0]), "+f"(c[1]), "+f"(c[2]), "+f"(c[3])
        : "r"(a[0]), "r"(a[1]), "r"(a[2]), "r"(a[3]), "r"(b[0]), "r"(b[1]));
}

// A-operand fragment (16 rows x k8) via one ldmatrix.x4.
__device__ __forceinline__ void ldsmA(uint32_t* r, const uint32_t* base,
                                      int row0, int ko, int lane, int S) {
    const uint32_t* p = base +
        (size_t)(row0 + (lane & 7) + ((lane >> 3) & 1) * 8) * S + ko + (lane >> 4) * 4;
    uint32_t addr = (uint32_t)__cvta_generic_to_shared(p);
    asm volatile("ldmatrix.sync.aligned.m8n8.x4.shared.b16 {%0,%1,%2,%3}, [%4];"
                 : "=r"(r[0]), "=r"(r[1]), "=r"(r[2]), "=r"(r[3]) : "r"(addr));
}

// Two B-operand fragments (cols n0..n0+15 x k8) via one ldmatrix.x4.
__device__ __forceinline__ void ldsmB2(uint32_t* r, const uint32_t* base,
                                       int n0, int ko, int lane, int S) {
    const uint32_t* p = base +
        (size_t)(n0 + ((lane >> 4) << 3) + (lane & 7)) * S + ko + ((lane >> 3) & 1) * 4;
    uint32_t addr = (uint32_t)__cvta_generic_to_shared(p);
    asm volatile("ldmatrix.sync.aligned.m8n8.x4.shared.b16 {%0,%1,%2,%3}, [%4];"
                 : "=r"(r[0]), "=r"(r[1]), "=r"(r[2]), "=r"(r[3]) : "r"(addr));
}

// ---------------------------------------------------------------------------
// Kernel 1: fused QKV projection, 2 heads per block.
// Block 128(M) x 128(N = 2 heads x 64), 8 warps of 64x32, K-tile 32.
// Register double-buffering: next tile's LDGs issue during current MMAs.
// ---------------------------------------------------------------------------
__global__ __launch_bounds__(256) void proj_kernel(const float* __restrict__ X,
                                                   const float* __restrict__ qw,
                                                   const float* __restrict__ kw,
                                                   const float* __restrict__ vw,
                                                   const float* __restrict__ qb,
                                                   const float* __restrict__ kb,
                                                   const float* __restrict__ vb,
                                                   float* __restrict__ oq,
                                                   float* __restrict__ ok,
                                                   float* __restrict__ ov)
{
    const float* W; const float* bias; float* out;
    if (blockIdx.z == 0)      { W = qw; bias = qb; out = oq; }
    else if (blockIdx.z == 1) { W = kw; bias = kb; out = ok; }
    else                      { W = vw; bias = vb; out = ov; }

    __shared__ __align__(16) uint32_t As[128][36];   // [m][k]
    __shared__ __align__(16) uint32_t Bs[128][36];   // [n][k]

    const int m0   = blockIdx.x * 128;
    const int h0   = blockIdx.y * 2;
    const int tid  = threadIdx.x;
    const int lane = tid & 31;
    const int warp = tid >> 5;
    const int wm   = warp >> 2;     // 0..1
    const int wn   = warp & 3;      // 0..3
    const int g    = lane >> 2;
    const int tg   = lane & 3;

    // index precompute for fills
    const int arow = tid >> 3,  ac = (tid & 7) * 4;          // + j*32 rows
    const int bn   = (tid >> 5) * 4, be = tid & 31;          // + j*32 n

    float4 ra[4], rb[4];
    #pragma unroll
    for (int j = 0; j < 4; j++) {
        ra[j] = *reinterpret_cast<const float4*>(
            X + (size_t)(m0 + arow + j * 32) * E_ + ac);
        int n = bn + j * 32;
        rb[j] = *reinterpret_cast<const float4*>(
            W + ((size_t)(h0 + (n >> 6)) * E_ + be) * D_ + (n & 63));
    }

    float acc[4][4][4] = {};

    for (int k0 = 0; k0 < E_; k0 += 32) {
        // STS current tile (with tf32 cvt)
        #pragma unroll
        for (int j = 0; j < 4; j++) {
            uint4 u;
            u.x = f2tf(ra[j].x); u.y = f2tf(ra[j].y);
            u.z = f2tf(ra[j].z); u.w = f2tf(ra[j].w);
            *reinterpret_cast<uint4*>(&As[arow + j * 32][ac]) = u;
            int n = bn + j * 32;
            Bs[n + 0][be] = f2tf(rb[j].x);
            Bs[n + 1][be] = f2tf(rb[j].y);
            Bs[n + 2][be] = f2tf(rb[j].z);
            Bs[n + 3][be] = f2tf(rb[j].w);
        }
        __syncthreads();

        // prefetch next tile (LDG overlaps MMAs below)
        if (k0 + 32 < E_) {
            #pragma unroll
            for (int j = 0; j < 4; j++) {
                ra[j] = *reinterpret_cast<const float4*>(
                    X + (size_t)(m0 + arow + j * 32) * E_ + k0 + 32 + ac);
                int n = bn + j * 32;
                rb[j] = *reinterpret_cast<const float4*>(
                    W + ((size_t)(h0 + (n >> 6)) * E_ + k0 + 32 + be) * D_ + (n & 63));
            }
        }

        #pragma unroll
        for (int ks = 0; ks < 4; ks++) {
            uint32_t a[4][4], b[8];
            #pragma unroll
            for (int mf = 0; mf < 4; mf++)
                ldsmA(a[mf], &As[0][0], wm * 64 + mf * 16, ks * 8, lane, 36);
            ldsmB2(&b[0], &Bs[0][0], wn * 32 + 0,  ks * 8, lane, 36);
            ldsmB2(&b[4], &Bs[0][0], wn * 32 + 16, ks * 8, lane, 36);
            #pragma unroll
            for (int mf = 0; mf < 4; mf++)
                #pragma unroll
                for (int nf = 0; nf < 4; nf++)
                    mma8(acc[mf][nf], a[mf], &b[nf * 2]);
        }
        __syncthreads();
    }

    // epilogue: out (B,H,T,D) + bias
    #pragma unroll
    for (int mf = 0; mf < 4; mf++) {
        #pragma unroll
        for (int half = 0; half < 2; half++) {
            int m  = m0 + wm * 64 + mf * 16 + g + half * 8;
            int bb = m >> 11;
            int t  = m & (T_ - 1);
            #pragma unroll
            for (int nf = 0; nf < 4; nf++) {
                int nn = wn * 32 + nf * 8 + 2 * tg;
                int h  = h0 + (nn >> 6);
                int d  = nn & 63;
                float2 val;
                val.x = acc[mf][nf][half * 2 + 0] + bias[h * D_ + d];
                val.y = acc[mf][nf][half * 2 + 1] + bias[h * D_ + d + 1];
                *reinterpret_cast<float2*>(
                    out + (((size_t)bb * H_ + h) * T_ + t) * D_ + d) = val;
            }
        }
    }
}

// ---------------------------------------------------------------------------
// Pass A: column softmax stats (log2 domain). Writes cs[s] = exp2(-m)/z.
// grid (s_tile=16, bh=32), block 256, 8 warps of 64t x 32s.
// ---------------------------------------------------------------------------
__global__ __launch_bounds__(256) void stats_kernel(const float* __restrict__ Q,
                                                    const float* __restrict__ K,
                                                    float* __restrict__ cs_out)
{
    extern __shared__ __align__(16) char smem_raw[];
    uint32_t* Ks = reinterpret_cast<uint32_t*>(smem_raw);                 // [128][68]
    uint32_t* Qs = Ks + 128 * 68;                                         // [128][68]
    float* redm = reinterpret_cast<float*>(Qs + 128 * 68);                // [2][128]
    float* redz = redm + 256;                                             // [2][128]
    float* mrun = redz + 256;                                             // [128]
    float* zrun = mrun + 128;                                             // [128]

    const int st   = blockIdx.x;
    const int bh   = blockIdx.y;
    const int tid  = threadIdx.x;
    const int lane = tid & 31;
    const int warp = tid >> 5;
    const int wm   = warp >> 2;
    const int wn   = warp & 3;
    const int g    = lane >> 2;
    const int tg   = lane & 3;

    const float* Kp = K + ((size_t)bh * T_ + st * 128) * D_;
    #pragma unroll
    for (int j = 0; j < 8; j++) {
        int q = tid + j * 256;
        int row = q >> 4, c = (q & 15) * 4;
        float4 v = *reinterpret_cast<const float4*>(Kp + (size_t)row * D_ + c);
        uint4 u;
        u.x = f2tf(v.x); u.y = f2tf(v.y); u.z = f2tf(v.z); u.w = f2tf(v.w);
        *reinterpret_cast<uint4*>(Ks + row * 68 + c) = u;
    }
    if (tid < 128) { mrun[tid] = -3.0e38f; zrun[tid] = 0.f; }
    __syncthreads();

    for (int it = st; it < T_ / 128; it++) {
        const float* Qp = Q + ((size_t)bh * T_ + it * 128) * D_;
        #pragma unroll
        for (int j = 0; j < 8; j++) {
            int q = tid + j * 256;
            int row = q >> 4, c = (q & 15) * 4;
            float4 v = *reinterpret_cast<const float4*>(Qp + (size_t)row * D_ + c);
            uint4 u;
            u.x = f2tf(v.x); u.y = f2tf(v.y); u.z = f2tf(v.z); u.w = f2tf(v.w);
            *reinterpret_cast<uint4*>(Qs + row * 68 + c) = u;
        }
        __syncthreads();

        float acc[4][4][4] = {};
        #pragma unroll
        for (int ks = 0; ks < 8; ks++) {
            uint32_t a[4][4], b[8];
            #pragma unroll
            for (int mf = 0; mf < 4; mf++)
                ldsmA(a[mf], Qs, wm * 64 + mf * 16, ks * 8, lane, 68);
            ldsmB2(&b[0], Ks, wn * 32 + 0,  ks * 8, lane, 68);
            ldsmB2(&b[4], Ks, wn * 32 + 16, ks * 8, lane, 68);
            #pragma unroll
            for (int mf = 0; mf < 4; mf++)
                #pragma unroll
                for (int nf = 0; nf < 4; nf++)
                    mma8(acc[mf][nf], a[mf], &b[nf * 2]);
        }

        // scale to log2 domain + causal mask (diag tile only)
        if (it == st) {
            #pragma unroll
            for (int mf = 0; mf < 4; mf++)
                #pragma unroll
                for (int hh = 0; hh < 2; hh++) {
                    int tl = wm * 64 + mf * 16 + g + hh * 8;
                    #pragma unroll
                    for (int nf = 0; nf < 4; nf++)
                        #pragma unroll
                        for (int ci = 0; ci < 2; ci++) {
                            int sl = wn * 32 + nf * 8 + 2 * tg + ci;
                            float x = acc[mf][nf][hh * 2 + ci] * KS2;
                            acc[mf][nf][hh * 2 + ci] = (tl >= sl) ? x : -3.0e38f;
                        }
                }
        } else {
            #pragma unroll
            for (int mf = 0; mf < 4; mf++)
                #pragma unroll
                for (int nf = 0; nf < 4; nf++)
                    #pragma unroll
                    for (int c = 0; c < 4; c++)
                        acc[mf][nf][c] *= KS2;
        }

        // per-warp column max
        #pragma unroll
        for (int nf = 0; nf < 4; nf++)
            #pragma unroll
            for (int ci = 0; ci < 2; ci++) {
                float v = -3.0e38f;
                #pragma unroll
                for (int mf = 0; mf < 4; mf++) {
                    v = fmaxf(v, acc[mf][nf][ci]);
                    v = fmaxf(v, acc[mf][nf][2 + ci]);
                }
                v = fmaxf(v, __shfl_xor_sync(0xffffffffu, v, 4));
                v = fmaxf(v, __shfl_xor_sync(0xffffffffu, v, 8));
                v = fmaxf(v, __shfl_xor_sync(0xffffffffu, v, 16));
                if (lane < 4) redm[wm * 128 + wn * 32 + nf * 8 + 2 * tg + ci] = v;
            }
        __syncthreads();

        // exp2-sum with combined tile max
        #pragma unroll
        for (int nf = 0; nf < 4; nf++)
            #pragma unroll
            for (int ci = 0; ci < 2; ci++) {
                int col = wn * 32 + nf * 8 + 2 * tg + ci;
                float mt = fmaxf(redm[col], redm[128 + col]);
                float zs = 0.f;
                #pragma unroll
                for (int mf = 0; mf < 4; mf++) {
                    zs += fex2(acc[mf][nf][ci] - mt);
                    zs += fex2(acc[mf][nf][2 + ci] - mt);
                }
                zs += __shfl_xor_sync(0xffffffffu, zs, 4);
                zs += __shfl_xor_sync(0xffffffffu, zs, 8);
                zs += __shfl_xor_sync(0xffffffffu, zs, 16);
                if (lane < 4) redz[wm * 128 + col] = zs;
            }
        __syncthreads();

        if (tid < 128) {
            float mt = fmaxf(redm[tid], redm[128 + tid]);
            float zt = redz[tid] + redz[128 + tid];
            float mo = mrun[tid];
            float mn = fmaxf(mo, mt);
            zrun[tid] = zrun[tid] * fex2(mo - mn) + zt * fex2(mt - mn);
            mrun[tid] = mn;
        }
        __syncthreads();
    }

    if (tid < 128) {
        int s = st * 128 + tid;
        cs_out[bh * T_ + s] = fex2(-mrun[tid]) / zrun[tid];
    }
}

// ---------------------------------------------------------------------------
// Pass B: out = P @ V with p[t,s] = exp2(KS2*qk[t,s]) * cs[s].
// grid (t_tile=16 reversed, bh=32), block 256.
// Register double-buffering of K/V chunks; QK tile 64t x 16s, PV 32t x 32d.
// ---------------------------------------------------------------------------
__global__ __launch_bounds__(256) void out_kernel(const float* __restrict__ Q,
                                                  const float* __restrict__ K,
                                                  const float* __restrict__ V,
                                                  const float* __restrict__ cs_g,
                                                  float* __restrict__ out)
{
    extern __shared__ __align__(16) char smem_raw[];
    uint32_t* Qs = reinterpret_cast<uint32_t*>(smem_raw);  // [128][68]
    uint32_t* Ps = Qs + 128 * 68;                          // [128][68]
    uint32_t* Ks = Ps + 128 * 68;                          // [64][68]
    uint32_t* Vs = Ks + 64 * 68;                           // [64][68]
    float* cs    = reinterpret_cast<float*>(Vs + 64 * 68); // [64]

    const int tt   = (T_ / 128 - 1) - blockIdx.x;
    const int bh   = blockIdx.y;
    const int bb   = bh >> 4;
    const int h    = bh & 15;
    const int tid  = threadIdx.x;
    const int lane = tid & 31;
    const int warp = tid >> 5;
    const int g    = lane >> 2;
    const int tg   = lane & 3;

    const int wq_m = warp >> 2, wq_n = warp & 3;
    const int wp_m = warp & 3,  wp_n = warp >> 2;

    const int t0 = tt * 128;
    const int krow = tid >> 4, kc = (tid & 15) * 4;   // +j*16 rows

    const float* Qp = Q + ((size_t)bh * T_ + t0) * D_;
    #pragma unroll
    for (int j = 0; j < 8; j++) {
        int q = tid + j * 256;
        int row = q >> 4, c = (q & 15) * 4;
        float4 v = *reinterpret_cast<const float4*>(Qp + (size_t)row * D_ + c);
        uint4 u;
        u.x = f2tf(v.x); u.y = f2tf(v.y); u.z = f2tf(v.z); u.w = f2tf(v.w);
        *reinterpret_cast<uint4*>(Qs + row * 68 + c) = u;
    }

    const float* Kb = K + (size_t)bh * T_ * D_;
    const float* Vb = V + (size_t)bh * T_ * D_;

    // prefetch chunk 0
    float4 rk[4], rv[4];
    float rc = 0.f;
    #pragma unroll
    for (int j = 0; j < 4; j++) {
        rk[j] = *reinterpret_cast<const float4*>(Kb + (size_t)(krow + j * 16) * D_ + kc);
        rv[j] = *reinterpret_cast<const float4*>(Vb + (size_t)(krow + j * 16) * D_ + kc);
    }
    if (tid < 64) rc = cs_g[bh * T_ + tid];

    float oacc[2][4][4] = {};

    for (int s0 = 0; s0 <= t0 + 64; s0 += 64) {
        __syncthreads();   // prev PV done reading Ps/Vs (and Q STS on first iter)

        // STS current K/V chunk + cs
        #pragma unroll
        for (int j = 0; j < 4; j++) {
            int row = krow + j * 16;
            uint4 uk;
            uk.x = f2tf(rk[j].x); uk.y = f2tf(rk[j].y);
            uk.z = f2tf(rk[j].z); uk.w = f2tf(rk[j].w);
            *reinterpret_cast<uint4*>(Ks + row * 68 + kc) = uk;
            uint4 uv;
            uv.x = f2tf(rv[j].x); uv.y = f2tf(rv[j].y);
            uv.z = f2tf(rv[j].z); uv.w = f2tf(rv[j].w);
            *reinterpret_cast<uint4*>(Vs + row * 68 + kc) = uv;
        }
        if (tid < 64) cs[tid] = rc;
        __syncthreads();

        // prefetch next chunk (overlaps QK/PV MMAs)
        if (s0 + 64 <= t0 + 64) {
            int sn = s0 + 64;
            #pragma unroll
            for (int j = 0; j < 4; j++) {
                rk[j] = *reinterpret_cast<const float4*>(
                    Kb + (size_t)(sn + krow + j * 16) * D_ + kc);
                rv[j] = *reinterpret_cast<const float4*>(
                    Vb + (size_t)(sn + krow + j * 16) * D_ + kc);
            }
            if (tid < 64) rc = cs_g[bh * T_ + sn + tid];
        }

        // QK chunk: 128t x 64s
        float sacc[4][2][4] = {};
        #pragma unroll
        for (int ks = 0; ks < 8; ks++) {
            uint32_t a[4][4], b[4];
            #pragma unroll
            for (int mf = 0; mf < 4; mf++)
                ldsmA(a[mf], Qs, wq_m * 64 + mf * 16, ks * 8, lane, 68);
            ldsmB2(&b[0], Ks, wq_n * 16, ks * 8, lane, 68);
            #pragma unroll
            for (int mf = 0; mf < 4; mf++)
                #pragma unroll
                for (int nf = 0; nf < 2; nf++)
                    mma8(sacc[mf][nf], a[mf], &b[nf * 2]);
        }

        // p = exp2(KS2 * qk) * cs[s], causal mask on diag chunks
        const bool needmask = (s0 + 63 > t0);
        #pragma unroll
        for (int mf = 0; mf < 4; mf++)
            #pragma unroll
            for (int hh = 0; hh < 2; hh++) {
                int tl = wq_m * 64 + mf * 16 + g + hh * 8;
                #pragma unroll
                for (int nf = 0; nf < 2; nf++)
                    #pragma unroll
                    for (int ci = 0; ci < 2; ci++) {
                        int sl = wq_n * 16 + nf * 8 + 2 * tg + ci;
                        float p = fex2(sacc[mf][nf][hh * 2 + ci] * KS2) * cs[sl];
                        if (needmask && (s0 + sl > t0 + tl)) p = 0.f;
                        Ps[tl * 68 + sl] = f2tf(p);
                    }
            }
        __syncthreads();

        // PV: 128t x 64d over k=64
        #pragma unroll
        for (int ks = 0; ks < 8; ks++) {
            uint32_t a[2][4], b[4][2];
            #pragma unroll
            for (int mf = 0; mf < 2; mf++)
                ldsmA(a[mf], Ps, wp_m * 32 + mf * 16, ks * 8, lane, 68);
            #pragma unroll
            for (int nf = 0; nf < 4; nf++) {
                int cn = wp_n * 32 + nf * 8 + g;
                b[nf][0] = Vs[(ks * 8 + tg) * 68 + cn];
                b[nf][1] = Vs[(ks * 8 + tg + 4) * 68 + cn];
            }
            #pragma unroll
            for (int mf = 0; mf < 2; mf++)
                #pragma unroll
                for (int nf = 0; nf < 4; nf++)
                    mma8(oacc[mf][nf], a[mf], b[nf]);
        }
    }

    // epilogue: (B,T,H,D) head-major concat
    #pragma unroll
    for (int mf = 0; mf < 2; mf++)
        #pragma unroll
        for (int hh = 0; hh < 2; hh++) {
            int t = t0 + wp_m * 32 + mf * 16 + g + hh * 8;
            #pragma unroll
            for (int nf = 0; nf < 4; nf++) {
                int d = wp_n * 32 + nf * 8 + 2 * tg;
                float2 val;
                val.x = oacc[mf][nf][hh * 2 + 0];
                val.y = oacc[mf][nf][hh * 2 + 1];
                *reinterpret_cast<float2*>(
                    out + (((size_t)bb * T_ + t) * H_ + h) * D_ + d) = val;
            }
        }
}

// ---------------------------------------------------------------------------
// Launch
// ---------------------------------------------------------------------------
extern "C" void kernel_launch(void* const* d_in, const int* in_sizes, int n_in,
                              void* d_out, int out_size)
{
    const float* X   = (const float*)d_in[0];
    const float* k_w = (const float*)d_in[1];
    const float* k_b = (const float*)d_in[2];
    const float* q_w = (const float*)d_in[3];
    const float* q_b = (const float*)d_in[4];
    const float* v_w = (const float*)d_in[5];
    const float* v_b = (const float*)d_in[6];
    float* out = (float*)d_out;

    float *pq, *pk, *pv, *pcs;
    cudaGetSymbolAddress((void**)&pq, g_q);
    cudaGetSymbolAddress((void**)&pk, g_k);
    cudaGetSymbolAddress((void**)&pv, g_v);
    cudaGetSymbolAddress((void**)&pcs, g_cs);

    const int SA = (2 * 128 * 68) * 4 + (256 + 256 + 128 + 128) * 4;        // 72704
    const int SB = (128 * 68 + 128 * 68 + 64 * 68 + 64 * 68) * 4 + 64 * 4;  // 104704

    cudaFuncSetAttribute(stats_kernel, cudaFuncAttributeMaxDynamicSharedMemorySize, SA);
    cudaFuncSetAttribute(out_kernel,   cudaFuncAttributeMaxDynamicSharedMemorySize, SB);

    dim3 projGrid(B_ * T_ / 128, H_ / 2, 3);   // (32, 8, 3)
    proj_kernel<<<projGrid, 256>>>(X, q_w, k_w, v_w, q_b, k_b, v_b, pq, pk, pv);

    dim3 stGrid(T_ / 128, BH_);
    stats_kernel<<<stGrid, 256, SA>>>(pq, pk, pcs);

    dim3 outGrid(T_ / 128, BH_);
    out_kernel<<<outGrid, 256, SB>>>(pq, pk, pv, pcs, out);
}

// round 9
// speedup vs baseline: 2.3916x; 2.2657x over previous
#include <cuda_runtime.h>
#include <cuda_fp16.h>
#include <cstdint>

#define B_  2
#define T_  2048
#define E_  1024
#define H_  16
#define D_  64
#define BH_ (B_*H_)       // 32

// scale * log2(e): softmax computed in base-2 domain
#define KS2 0.18033688011112042592f

// ---------------------------------------------------------------------------
// Device scratch (fp16 everywhere except column factors and final out)
// ---------------------------------------------------------------------------
__device__ __half g_xh[(size_t)B_ * T_ * E_];          // X in fp16
__device__ __half g_wh[(size_t)3 * H_ * E_ * D_];      // [z][h][e][d] fp16
__device__ __half g_q[(size_t)BH_ * T_ * D_];
__device__ __half g_k[(size_t)BH_ * T_ * D_];
__device__ __half g_v[(size_t)BH_ * T_ * D_];
__device__ float  g_cs[(size_t)BH_ * T_];              // exp2(-m)/z

// ---------------------------------------------------------------------------
// helpers
// ---------------------------------------------------------------------------
__device__ __forceinline__ float fex2(float x) {
    float r;
    asm("ex2.approx.f32 %0, %1;" : "=f"(r) : "f"(x));
    return r;
}

__device__ __forceinline__ void mma16(float* c, const uint32_t* a, const uint32_t* b) {
    asm("mma.sync.aligned.m16n8k16.row.col.f32.f16.f16.f32 "
        "{%0,%1,%2,%3},{%4,%5,%6,%7},{%8,%9},{%0,%1,%2,%3};"
        : "+f"(c[0]), "+f"(c[1]), "+f"(c[2]), "+f"(c[3])
        : "r"(a[0]), "r"(a[1]), "r"(a[2]), "r"(a[3]), "r"(b[0]), "r"(b[1]));
}

// A fragment (16m x 16k) from row-major [m][k] halves, stride S halves.
__device__ __forceinline__ void ldsmA16(uint32_t* r, const __half* base,
                                        int row0, int k0, int lane, int S) {
    const __half* p = base + (size_t)(row0 + (lane & 7) + ((lane >> 3) & 1) * 8) * S
                      + k0 + (lane >> 4) * 8;
    uint32_t a = (uint32_t)__cvta_generic_to_shared(p);
    asm volatile("ldmatrix.sync.aligned.m8n8.x4.shared.b16 {%0,%1,%2,%3}, [%4];"
                 : "=r"(r[0]), "=r"(r[1]), "=r"(r[2]), "=r"(r[3]) : "r"(a));
}

// Two B fragments (16n x 16k) from row-major [n][k] halves (non-trans).
__device__ __forceinline__ void ldsmBn16(uint32_t* r, const __half* base,
                                         int n0, int k0, int lane, int S) {
    const __half* p = base + (size_t)(n0 + (lane & 7) + (lane >> 4) * 8) * S
                      + k0 + ((lane >> 3) & 1) * 8;
    uint32_t a = (uint32_t)__cvta_generic_to_shared(p);
    asm volatile("ldmatrix.sync.aligned.m8n8.x4.shared.b16 {%0,%1,%2,%3}, [%4];"
                 : "=r"(r[0]), "=r"(r[1]), "=r"(r[2]), "=r"(r[3]) : "r"(a));
}

// Two B fragments (16n x 16k) from row-major [k][n] halves via ldmatrix.trans.
__device__ __forceinline__ void ldsmBt16(uint32_t* r, const __half* base,
                                         int n0, int k0, int lane, int S) {
    const __half* p = base + (size_t)(k0 + (lane & 7) + ((lane >> 3) & 1) * 8) * S
                      + n0 + (lane >> 4) * 8;
    uint32_t a = (uint32_t)__cvta_generic_to_shared(p);
    asm volatile("ldmatrix.sync.aligned.m8n8.x4.trans.shared.b16 {%0,%1,%2,%3}, [%4];"
                 : "=r"(r[0]), "=r"(r[1]), "=r"(r[2]), "=r"(r[3]) : "r"(a));
}

__device__ __forceinline__ void cpa16(void* smem_ptr, const void* g) {
    uint32_t a = (uint32_t)__cvta_generic_to_shared(smem_ptr);
    asm volatile("cp.async.cg.shared.global [%0], [%1], 16;" :: "r"(a), "l"(g));
}
__device__ __forceinline__ void cpa4(void* smem_ptr, const void* g) {
    uint32_t a = (uint32_t)__cvta_generic_to_shared(smem_ptr);
    asm volatile("cp.async.ca.shared.global [%0], [%1], 4;" :: "r"(a), "l"(g));
}
#define CP_COMMIT() asm volatile("cp.async.commit_group;" ::: "memory")
#define CP_WAIT(N)  asm volatile("cp.async.wait_group " #N ";" ::: "memory")

// ---------------------------------------------------------------------------
// Kernel 0: convert X and W (q,k,v) to fp16 scratch. grid 7168 x 256.
// ---------------------------------------------------------------------------
__global__ __launch_bounds__(256) void prep_kernel(const float* __restrict__ X,
                                                   const float* __restrict__ qw,
                                                   const float* __restrict__ kw,
                                                   const float* __restrict__ vw,
                                                   __half* __restrict__ Xh,
                                                   __half* __restrict__ Wh)
{
    const size_t XN4 = (size_t)B_ * T_ * E_ / 4;   // 1,048,576
    size_t i4 = (size_t)blockIdx.x * 256 + threadIdx.x;
    float4 v;
    uint2* dst;
    if (i4 < XN4) {
        v = reinterpret_cast<const float4*>(X)[i4];
        dst = reinterpret_cast<uint2*>(Xh) + i4;
    } else {
        size_t j = i4 - XN4;
        size_t base = j * 4;
        int z = (int)(base >> 20);                 // H*E*D = 2^20
        size_t rem = base & ((1u << 20) - 1);
        const float* W = (z == 0) ? qw : (z == 1) ? kw : vw;
        v = *reinterpret_cast<const float4*>(W + rem);
        dst = reinterpret_cast<uint2*>(Wh) + j;
    }
    __half2 lo = __floats2half2_rn(v.x, v.y);
    __half2 hi = __floats2half2_rn(v.z, v.w);
    uint2 u;
    u.x = *reinterpret_cast<uint32_t*>(&lo);
    u.y = *reinterpret_cast<uint32_t*>(&hi);
    *dst = u;
}

// ---------------------------------------------------------------------------
// Kernel 1: fused QKV projection, 2 heads per block.
// Block 128m x 128n, 8 warps of 64x32, K-tile 64, cp.async double-buffered.
// A: Xh row-major [m][k]; B: Wh natural [k][n] + ldmatrix.trans.
// ---------------------------------------------------------------------------
__global__ __launch_bounds__(256) void proj_kernel(const __half* __restrict__ Xh,
                                                   const __half* __restrict__ Wh,
                                                   const float* __restrict__ qb,
                                                   const float* __restrict__ kb,
                                                   const float* __restrict__ vb,
                                                   __half* __restrict__ oq,
                                                   __half* __restrict__ ok,
                                                   __half* __restrict__ ov)
{
    extern __shared__ __align__(16) __half sm[];
    __half* Ah = sm;                   // [2][128*72]
    __half* Bh = sm + 2 * 128 * 72;    // [2][64*136]

    const int z = blockIdx.z;
    const float* bias = (z == 0) ? qb : (z == 1) ? kb : vb;
    __half* out = (z == 0) ? oq : (z == 1) ? ok : ov;
    const __half* Wz = Wh + (size_t)z * H_ * E_ * D_;

    const int m0   = blockIdx.x * 128;
    const int h0   = blockIdx.y * 2;
    const int tid  = threadIdx.x;
    const int lane = tid & 31;
    const int warp = tid >> 5;
    const int wm   = warp >> 2;
    const int wn   = warp & 3;
    const int g    = lane >> 2;
    const int tg   = lane & 3;

    // fill helper pieces
    const int ar = tid >> 3, ac = (tid & 7) * 8;       // A: +j*32 rows, 8-half chunks
    const int br = tid >> 4, bc = tid & 15;            // B: +j*16 rows, 16 chunks/row

    auto issue = [&](int kt, int buf) {
        __half* Ad = Ah + buf * 128 * 72;
        #pragma unroll
        for (int j = 0; j < 4; j++) {
            int r = ar + j * 32;
            cpa16(Ad + (size_t)r * 72 + ac,
                  Xh + (size_t)(m0 + r) * E_ + kt * 64 + ac);
        }
        __half* Bd = Bh + buf * 64 * 136;
        #pragma unroll
        for (int j = 0; j < 4; j++) {
            int r = br + j * 16;
            int h = h0 + (bc >> 3);
            int d = (bc & 7) * 8;
            cpa16(Bd + (size_t)r * 136 + bc * 8,
                  Wz + ((size_t)h * E_ + kt * 64 + r) * D_ + d);
        }
    };

    issue(0, 0);
    CP_COMMIT();

    float acc[4][4][4] = {};

    for (int kt = 0; kt < 16; kt++) {
        int buf = kt & 1;
        if (kt < 15) {
            issue(kt + 1, buf ^ 1);
            CP_COMMIT();
            CP_WAIT(1);
        } else {
            CP_WAIT(0);
        }
        __syncthreads();

        const __half* At = Ah + buf * 128 * 72;
        const __half* Bt = Bh + buf * 64 * 136;
        #pragma unroll
        for (int ks = 0; ks < 4; ks++) {
            uint32_t a[4][4], b[8];
            #pragma unroll
            for (int mf = 0; mf < 4; mf++)
                ldsmA16(a[mf], At, wm * 64 + mf * 16, ks * 16, lane, 72);
            ldsmBt16(&b[0], Bt, wn * 32 + 0,  ks * 16, lane, 136);
            ldsmBt16(&b[4], Bt, wn * 32 + 16, ks * 16, lane, 136);
            #pragma unroll
            for (int mf = 0; mf < 4; mf++)
                #pragma unroll
                for (int nf = 0; nf < 4; nf++)
                    mma16(acc[mf][nf], a[mf], &b[nf * 2]);
        }
        __syncthreads();
    }

    // epilogue: fp16 Q/K/V (B,H,T,D) with fp32 bias add
    #pragma unroll
    for (int mf = 0; mf < 4; mf++) {
        #pragma unroll
        for (int hh = 0; hh < 2; hh++) {
            int m  = m0 + wm * 64 + mf * 16 + g + hh * 8;
            int bb = m >> 11;
            int t  = m & (T_ - 1);
            #pragma unroll
            for (int nf = 0; nf < 4; nf++) {
                int nn = wn * 32 + nf * 8 + 2 * tg;
                int h  = h0 + (nn >> 6);
                int d  = nn & 63;
                float v0 = acc[mf][nf][hh * 2 + 0] + bias[h * D_ + d];
                float v1 = acc[mf][nf][hh * 2 + 1] + bias[h * D_ + d + 1];
                *reinterpret_cast<__half2*>(
                    out + (((size_t)bb * H_ + h) * T_ + t) * D_ + d) =
                    __floats2half2_rn(v0, v1);
            }
        }
    }
}

// ---------------------------------------------------------------------------
// Pass A: column softmax stats (log2 domain). Writes cs[s] = exp2(-m)/z.
// grid (s_tile=16, bh=32), block 256, 8 warps of 64t x 32s. fp16 MMA k16.
// ---------------------------------------------------------------------------
__global__ __launch_bounds__(256) void stats_kernel(const __half* __restrict__ Q,
                                                    const __half* __restrict__ K,
                                                    float* __restrict__ cs_out)
{
    extern __shared__ __align__(16) __half sm[];
    __half* Ks = sm;                   // [128*72]  (B operand [s][d] = [n][k])
    __half* Qs = sm + 128 * 72;        // [2][128*72]
    float* redm = reinterpret_cast<float*>(sm + 3 * 128 * 72);   // [2][128]
    float* redz = redm + 256;                                    // [2][128]
    float* mrun = redz + 256;                                    // [128]
    float* zrun = mrun + 128;                                    // [128]

    const int st   = blockIdx.x;
    const int bh   = blockIdx.y;
    const int tid  = threadIdx.x;
    const int lane = tid & 31;
    const int warp = tid >> 5;
    const int wm   = warp >> 2;
    const int wn   = warp & 3;
    const int g    = lane >> 2;
    const int tg   = lane & 3;

    const int fr = tid >> 3, fc = (tid & 7) * 8;   // fill: +j*32 rows

    auto issueQ = [&](int it, int buf) {
        __half* Qd = Qs + buf * 128 * 72;
        const __half* Qp = Q + ((size_t)bh * T_ + it * 128) * D_;
        #pragma unroll
        for (int j = 0; j < 4; j++) {
            int r = fr + j * 32;
            cpa16(Qd + (size_t)r * 72 + fc, Qp + (size_t)r * D_ + fc);
        }
    };

    // prologue: K tile + first Q tile in one group
    {
        const __half* Kp = K + ((size_t)bh * T_ + st * 128) * D_;
        #pragma unroll
        for (int j = 0; j < 4; j++) {
            int r = fr + j * 32;
            cpa16(Ks + (size_t)r * 72 + fc, Kp + (size_t)r * D_ + fc);
        }
        issueQ(st, st & 1);
        CP_COMMIT();
    }
    if (tid < 128) { mrun[tid] = -3.0e38f; zrun[tid] = 0.f; }

    for (int it = st; it < T_ / 128; it++) {
        int buf = it & 1;
        if (it < 15) {
            issueQ(it + 1, buf ^ 1);
            CP_COMMIT();
            CP_WAIT(1);
        } else {
            CP_WAIT(0);
        }
        __syncthreads();

        const __half* Qt = Qs + buf * 128 * 72;
        float acc[4][4][4] = {};
        #pragma unroll
        for (int ks = 0; ks < 4; ks++) {
            uint32_t a[4][4], b[8];
            #pragma unroll
            for (int mf = 0; mf < 4; mf++)
                ldsmA16(a[mf], Qt, wm * 64 + mf * 16, ks * 16, lane, 72);
            ldsmBn16(&b[0], Ks, wn * 32 + 0,  ks * 16, lane, 72);
            ldsmBn16(&b[4], Ks, wn * 32 + 16, ks * 16, lane, 72);
            #pragma unroll
            for (int mf = 0; mf < 4; mf++)
                #pragma unroll
                for (int nf = 0; nf < 4; nf++)
                    mma16(acc[mf][nf], a[mf], &b[nf * 2]);
        }

        // scale to log2 domain + causal mask (diag tile only)
        if (it == st) {
            #pragma unroll
            for (int mf = 0; mf < 4; mf++)
                #pragma unroll
                for (int hh = 0; hh < 2; hh++) {
                    int tl = wm * 64 + mf * 16 + g + hh * 8;
                    #pragma unroll
                    for (int nf = 0; nf < 4; nf++)
                        #pragma unroll
                        for (int ci = 0; ci < 2; ci++) {
                            int sl = wn * 32 + nf * 8 + 2 * tg + ci;
                            float x = acc[mf][nf][hh * 2 + ci] * KS2;
                            acc[mf][nf][hh * 2 + ci] = (tl >= sl) ? x : -3.0e38f;
                        }
                }
        } else {
            #pragma unroll
            for (int mf = 0; mf < 4; mf++)
                #pragma unroll
                for (int nf = 0; nf < 4; nf++)
                    #pragma unroll
                    for (int c = 0; c < 4; c++)
                        acc[mf][nf][c] *= KS2;
        }

        // per-warp column max
        #pragma unroll
        for (int nf = 0; nf < 4; nf++)
            #pragma unroll
            for (int ci = 0; ci < 2; ci++) {
                float v = -3.0e38f;
                #pragma unroll
                for (int mf = 0; mf < 4; mf++) {
                    v = fmaxf(v, acc[mf][nf][ci]);
                    v = fmaxf(v, acc[mf][nf][2 + ci]);
                }
                v = fmaxf(v, __shfl_xor_sync(0xffffffffu, v, 4));
                v = fmaxf(v, __shfl_xor_sync(0xffffffffu, v, 8));
                v = fmaxf(v, __shfl_xor_sync(0xffffffffu, v, 16));
                if (lane < 4) redm[wm * 128 + wn * 32 + nf * 8 + 2 * tg + ci] = v;
            }
        __syncthreads();

        // exp2-sum with combined tile max
        #pragma unroll
        for (int nf = 0; nf < 4; nf++)
            #pragma unroll
            for (int ci = 0; ci < 2; ci++) {
                int col = wn * 32 + nf * 8 + 2 * tg + ci;
                float mt = fmaxf(redm[col], redm[128 + col]);
                float zs = 0.f;
                #pragma unroll
                for (int mf = 0; mf < 4; mf++) {
                    zs += fex2(acc[mf][nf][ci] - mt);
                    zs += fex2(acc[mf][nf][2 + ci] - mt);
                }
                zs += __shfl_xor_sync(0xffffffffu, zs, 4);
                zs += __shfl_xor_sync(0xffffffffu, zs, 8);
                zs += __shfl_xor_sync(0xffffffffu, zs, 16);
                if (lane < 4) redz[wm * 128 + col] = zs;
            }
        __syncthreads();

        if (tid < 128) {
            float mt = fmaxf(redm[tid], redm[128 + tid]);
            float zt = redz[tid] + redz[128 + tid];
            float mo = mrun[tid];
            float mn = fmaxf(mo, mt);
            zrun[tid] = zrun[tid] * fex2(mo - mn) + zt * fex2(mt - mn);
            mrun[tid] = mn;
        }
        __syncthreads();
    }

    if (tid < 128) {
        int s = st * 128 + tid;
        cs_out[bh * T_ + s] = fex2(-mrun[tid]) / zrun[tid];
    }
}

// ---------------------------------------------------------------------------
// Pass B: out = P @ V with p[t,s] = exp2(KS2*qk) * cs[s]. fp16 MMA k16.
// grid (t_tile=16 reversed, bh=32), block 256. K/V/cs double-buffered cp.async.
// QK warp tile 64t x 16s; PV warp tile 32t x 32d.
// ---------------------------------------------------------------------------
__global__ __launch_bounds__(256) void out_kernel(const __half* __restrict__ Q,
                                                  const __half* __restrict__ K,
                                                  const __half* __restrict__ V,
                                                  const float* __restrict__ cs_g,
                                                  float* __restrict__ out)
{
    extern __shared__ __align__(16) __half sm[];
    __half* Qs  = sm;                        // [128*72]
    __half* Ps  = sm + 128 * 72;             // [128*72]
    __half* Ksm = sm + 2 * 128 * 72;         // [2][64*72]  ([s][d] non-trans B)
    __half* Vsm = Ksm + 2 * 64 * 72;         // [2][64*72]  ([s][d] trans B)
    float*  cs  = reinterpret_cast<float*>(Vsm + 2 * 64 * 72);   // [2][64]

    const int tt   = (T_ / 128 - 1) - blockIdx.x;
    const int bh   = blockIdx.y;
    const int bb   = bh >> 4;
    const int h    = bh & 15;
    const int tid  = threadIdx.x;
    const int lane = tid & 31;
    const int warp = tid >> 5;
    const int g    = lane >> 2;
    const int tg   = lane & 3;

    const int wq_m = warp >> 2, wq_n = warp & 3;
    const int wp_m = warp & 3,  wp_n = warp >> 2;

    const int t0  = tt * 128;
    const int nch = 2 * tt + 2;

    const int fr = tid >> 3, fc = (tid & 7) * 8;

    const __half* Kb = K + (size_t)bh * T_ * D_;
    const __half* Vb = V + (size_t)bh * T_ * D_;

    auto issueKV = [&](int ic, int buf) {
        const __half* Kp = Kb + (size_t)ic * 64 * D_;
        const __half* Vp = Vb + (size_t)ic * 64 * D_;
        __half* Kd = Ksm + buf * 64 * 72;
        __half* Vd = Vsm + buf * 64 * 72;
        #pragma unroll
        for (int j = 0; j < 2; j++) {
            int r = fr + j * 32;
            cpa16(Kd + (size_t)r * 72 + fc, Kp + (size_t)r * D_ + fc);
            cpa16(Vd + (size_t)r * 72 + fc, Vp + (size_t)r * D_ + fc);
        }
        if (tid < 64) cpa4(cs + buf * 64 + tid, cs_g + (size_t)bh * T_ + ic * 64 + tid);
    };

    // prologue: Q tile + chunk0 (group 0), chunk1 (group 1)
    {
        const __half* Qp = Q + ((size_t)bh * T_ + t0) * D_;
        #pragma unroll
        for (int j = 0; j < 4; j++) {
            int r = fr + j * 32;
            cpa16(Qs + (size_t)r * 72 + fc, Qp + (size_t)r * D_ + fc);
        }
        issueKV(0, 0);
        CP_COMMIT();
        issueKV(1, 1);
        CP_COMMIT();
    }

    float oacc[2][4][4] = {};

    for (int ic = 0; ic < nch; ic++) {
        if (ic + 1 < nch) { CP_WAIT(1); } else { CP_WAIT(0); }
        __syncthreads();

        const int s0  = ic * 64;
        const int buf = ic & 1;
        const __half* Kt = Ksm + buf * 64 * 72;
        const __half* Vt = Vsm + buf * 64 * 72;
        const float*  cb = cs + buf * 64;

        // QK chunk: 128t x 64s
        float sacc[4][2][4] = {};
        #pragma unroll
        for (int ks = 0; ks < 4; ks++) {
            uint32_t a[4][4], b[4];
            #pragma unroll
            for (int mf = 0; mf < 4; mf++)
                ldsmA16(a[mf], Qs, wq_m * 64 + mf * 16, ks * 16, lane, 72);
            ldsmBn16(&b[0], Kt, wq_n * 16, ks * 16, lane, 72);
            #pragma unroll
            for (int mf = 0; mf < 4; mf++)
                #pragma unroll
                for (int nf = 0; nf < 2; nf++)
                    mma16(sacc[mf][nf], a[mf], &b[nf * 2]);
        }

        // p = exp2(KS2*qk) * cs[s]; causal mask on diag chunks; stage P as fp16
        const bool needmask = (s0 + 63 > t0);
        #pragma unroll
        for (int mf = 0; mf < 4; mf++)
            #pragma unroll
            for (int hh = 0; hh < 2; hh++) {
                int tl = wq_m * 64 + mf * 16 + g + hh * 8;
                #pragma unroll
                for (int nf = 0; nf < 2; nf++) {
                    int sl = wq_n * 16 + nf * 8 + 2 * tg;
                    float p0 = fex2(sacc[mf][nf][hh * 2 + 0] * KS2) * cb[sl];
                    float p1 = fex2(sacc[mf][nf][hh * 2 + 1] * KS2) * cb[sl + 1];
                    if (needmask) {
                        if (s0 + sl > t0 + tl)     p0 = 0.f;
                        if (s0 + sl + 1 > t0 + tl) p1 = 0.f;
                    }
                    *reinterpret_cast<__half2*>(Ps + (size_t)tl * 72 + sl) =
                        __floats2half2_rn(p0, p1);
                }
            }
        __syncthreads();

        // PV: 128t x 64d over k=64
        #pragma unroll
        for (int ks = 0; ks < 4; ks++) {
            uint32_t a[2][4], b[8];
            #pragma unroll
            for (int mf = 0; mf < 2; mf++)
                ldsmA16(a[mf], Ps, wp_m * 32 + mf * 16, ks * 16, lane, 72);
            ldsmBt16(&b[0], Vt, wp_n * 32 + 0,  ks * 16, lane, 72);
            ldsmBt16(&b[4], Vt, wp_n * 32 + 16, ks * 16, lane, 72);
            #pragma unroll
            for (int mf = 0; mf < 2; mf++)
                #pragma unroll
                for (int nf = 0; nf < 4; nf++)
                    mma16(oacc[mf][nf], a[mf], &b[nf * 2]);
        }
        __syncthreads();   // all PV reads of buf done before reissue

        if (ic + 2 < nch) {
            issueKV(ic + 2, buf);
            CP_COMMIT();
        }
    }

    // epilogue: (B,T,H,D) head-major concat, fp32
    #pragma unroll
    for (int mf = 0; mf < 2; mf++)
        #pragma unroll
        for (int hh = 0; hh < 2; hh++) {
            int t = t0 + wp_m * 32 + mf * 16 + g + hh * 8;
            #pragma unroll
            for (int nf = 0; nf < 4; nf++) {
                int d = wp_n * 32 + nf * 8 + 2 * tg;
                float2 val;
                val.x = oacc[mf][nf][hh * 2 + 0];
                val.y = oacc[mf][nf][hh * 2 + 1];
                *reinterpret_cast<float2*>(
                    out + (((size_t)bb * T_ + t) * H_ + h) * D_ + d) = val;
            }
        }
}

// ---------------------------------------------------------------------------
// Launch
// ---------------------------------------------------------------------------
extern "C" void kernel_launch(void* const* d_in, const int* in_sizes, int n_in,
                              void* d_out, int out_size)
{
    const float* X   = (const float*)d_in[0];
    const float* k_w = (const float*)d_in[1];
    const float* k_b = (const float*)d_in[2];
    const float* q_w = (const float*)d_in[3];
    const float* q_b = (const float*)d_in[4];
    const float* v_w = (const float*)d_in[5];
    const float* v_b = (const float*)d_in[6];
    float* out = (float*)d_out;

    __half *pxh, *pwh, *pq, *pk, *pv;
    float* pcs;
    cudaGetSymbolAddress((void**)&pxh, g_xh);
    cudaGetSymbolAddress((void**)&pwh, g_wh);
    cudaGetSymbolAddress((void**)&pq, g_q);
    cudaGetSymbolAddress((void**)&pk, g_k);
    cudaGetSymbolAddress((void**)&pv, g_v);
    cudaGetSymbolAddress((void**)&pcs, g_cs);

    const int SP = (2 * 128 * 72 + 2 * 64 * 136) * 2;                  // 71680
    const int SA = 3 * 128 * 72 * 2 + (256 + 256 + 128 + 128) * 4;     // 58368
    const int SB = (2 * 128 * 72 + 4 * 64 * 72) * 2 + 2 * 64 * 4;      // 74240

    cudaFuncSetAttribute(proj_kernel,  cudaFuncAttributeMaxDynamicSharedMemorySize, SP);
    cudaFuncSetAttribute(stats_kernel, cudaFuncAttributeMaxDynamicSharedMemorySize, SA);
    cudaFuncSetAttribute(out_kernel,   cudaFuncAttributeMaxDynamicSharedMemorySize, SB);

    prep_kernel<<<7168, 256>>>(X, q_w, k_w, v_w, pxh, pwh);

    dim3 projGrid(B_ * T_ / 128, H_ / 2, 3);   // (32, 8, 3)
    proj_kernel<<<projGrid, 256, SP>>>(pxh, pwh, q_b, k_b, v_b, pq, pk, pv);

    dim3 stGrid(T_ / 128, BH_);
    stats_kernel<<<stGrid, 256, SA>>>(pq, pk, pcs);

    dim3 outGrid(T_ / 128, BH_);
    out_kernel<<<outGrid, 256, SB>>>(pq, pk, pv, pcs, out);
}

// round 10
// speedup vs baseline: 2.5659x; 1.0729x over previous
#include <cuda_runtime.h>
#include <cuda_fp16.h>
#include <cstdint>

#define B_  2
#define T_  2048
#define E_  1024
#define H_  16
#define D_  64
#define BH_ (B_*H_)       // 32

// scale * log2(e): softmax computed in base-2 domain (folded into Q at proj)
#define KS2 0.18033688011112042592f

// ---------------------------------------------------------------------------
// Device scratch
// ---------------------------------------------------------------------------
__device__ __half g_xh[(size_t)B_ * T_ * E_];
__device__ __half g_wh[(size_t)3 * H_ * E_ * D_];
__device__ __half g_q[(size_t)BH_ * T_ * D_];      // pre-scaled by KS2
__device__ __half g_k[(size_t)BH_ * T_ * D_];
__device__ __half g_v[(size_t)BH_ * T_ * D_];
__device__ float  g_cs[(size_t)BH_ * T_];          // exp2(-m)/z

// ---------------------------------------------------------------------------
// helpers
// ---------------------------------------------------------------------------
__device__ __forceinline__ float fex2(float x) {
    float r;
    asm("ex2.approx.f32 %0, %1;" : "=f"(r) : "f"(x));
    return r;
}

__device__ __forceinline__ void mma16(float* c, const uint32_t* a, const uint32_t* b) {
    asm("mma.sync.aligned.m16n8k16.row.col.f32.f16.f16.f32 "
        "{%0,%1,%2,%3},{%4,%5,%6,%7},{%8,%9},{%0,%1,%2,%3};"
        : "+f"(c[0]), "+f"(c[1]), "+f"(c[2]), "+f"(c[3])
        : "r"(a[0]), "r"(a[1]), "r"(a[2]), "r"(a[3]), "r"(b[0]), "r"(b[1]));
}

__device__ __forceinline__ void ldsmA16(uint32_t* r, const __half* base,
                                        int row0, int k0, int lane, int S) {
    const __half* p = base + (size_t)(row0 + (lane & 7) + ((lane >> 3) & 1) * 8) * S
                      + k0 + (lane >> 4) * 8;
    uint32_t a = (uint32_t)__cvta_generic_to_shared(p);
    asm volatile("ldmatrix.sync.aligned.m8n8.x4.shared.b16 {%0,%1,%2,%3}, [%4];"
                 : "=r"(r[0]), "=r"(r[1]), "=r"(r[2]), "=r"(r[3]) : "r"(a));
}

__device__ __forceinline__ void ldsmBn16(uint32_t* r, const __half* base,
                                         int n0, int k0, int lane, int S) {
    const __half* p = base + (size_t)(n0 + (lane & 7) + (lane >> 4) * 8) * S
                      + k0 + ((lane >> 3) & 1) * 8;
    uint32_t a = (uint32_t)__cvta_generic_to_shared(p);
    asm volatile("ldmatrix.sync.aligned.m8n8.x4.shared.b16 {%0,%1,%2,%3}, [%4];"
                 : "=r"(r[0]), "=r"(r[1]), "=r"(r[2]), "=r"(r[3]) : "r"(a));
}

__device__ __forceinline__ void ldsmBt16(uint32_t* r, const __half* base,
                                         int n0, int k0, int lane, int S) {
    const __half* p = base + (size_t)(k0 + (lane & 7) + ((lane >> 3) & 1) * 8) * S
                      + n0 + (lane >> 4) * 8;
    uint32_t a = (uint32_t)__cvta_generic_to_shared(p);
    asm volatile("ldmatrix.sync.aligned.m8n8.x4.trans.shared.b16 {%0,%1,%2,%3}, [%4];"
                 : "=r"(r[0]), "=r"(r[1]), "=r"(r[2]), "=r"(r[3]) : "r"(a));
}

__device__ __forceinline__ void cpa16(void* smem_ptr, const void* g) {
    uint32_t a = (uint32_t)__cvta_generic_to_shared(smem_ptr);
    asm volatile("cp.async.cg.shared.global [%0], [%1], 16;" :: "r"(a), "l"(g));
}
__device__ __forceinline__ void cpa4(void* smem_ptr, const void* g) {
    uint32_t a = (uint32_t)__cvta_generic_to_shared(smem_ptr);
    asm volatile("cp.async.ca.shared.global [%0], [%1], 4;" :: "r"(a), "l"(g));
}
#define CP_COMMIT() asm volatile("cp.async.commit_group;" ::: "memory")
#define CP_WAIT(N)  asm volatile("cp.async.wait_group " #N ";" ::: "memory")

// ---------------------------------------------------------------------------
// Kernel 0: convert X and W to fp16 scratch.
// ---------------------------------------------------------------------------
__global__ __launch_bounds__(256) void prep_kernel(const float* __restrict__ X,
                                                   const float* __restrict__ qw,
                                                   const float* __restrict__ kw,
                                                   const float* __restrict__ vw,
                                                   __half* __restrict__ Xh,
                                                   __half* __restrict__ Wh)
{
    const size_t XN4 = (size_t)B_ * T_ * E_ / 4;
    size_t i4 = (size_t)blockIdx.x * 256 + threadIdx.x;
    float4 v;
    uint2* dst;
    if (i4 < XN4) {
        v = reinterpret_cast<const float4*>(X)[i4];
        dst = reinterpret_cast<uint2*>(Xh) + i4;
    } else {
        size_t j = i4 - XN4;
        size_t base = j * 4;
        int z = (int)(base >> 20);
        size_t rem = base & ((1u << 20) - 1);
        const float* W = (z == 0) ? qw : (z == 1) ? kw : vw;
        v = *reinterpret_cast<const float4*>(W + rem);
        dst = reinterpret_cast<uint2*>(Wh) + j;
    }
    __half2 lo = __floats2half2_rn(v.x, v.y);
    __half2 hi = __floats2half2_rn(v.z, v.w);
    uint2 u;
    u.x = *reinterpret_cast<uint32_t*>(&lo);
    u.y = *reinterpret_cast<uint32_t*>(&hi);
    *dst = u;
}

// ---------------------------------------------------------------------------
// Kernel 1: fused QKV projection. 128m x 128n block, 8 warps of 64x32.
// Triple-buffered cp.async, ONE barrier per K-tile. Q output scaled by KS2.
// ---------------------------------------------------------------------------
__global__ __launch_bounds__(256) void proj_kernel(const __half* __restrict__ Xh,
                                                   const __half* __restrict__ Wh,
                                                   const float* __restrict__ qb,
                                                   const float* __restrict__ kb,
                                                   const float* __restrict__ vb,
                                                   __half* __restrict__ oq,
                                                   __half* __restrict__ ok,
                                                   __half* __restrict__ ov)
{
    extern __shared__ __align__(16) __half sm[];
    __half* Ah = sm;                     // [3][128*72]
    __half* Bh = sm + 3 * 128 * 72;      // [3][64*136]

    const int z = blockIdx.z;
    const float* bias = (z == 0) ? qb : (z == 1) ? kb : vb;
    __half* out = (z == 0) ? oq : (z == 1) ? ok : ov;
    const float osc = (z == 0) ? KS2 : 1.0f;
    const __half* Wz = Wh + (size_t)z * H_ * E_ * D_;

    const int m0   = blockIdx.x * 128;
    const int h0   = blockIdx.y * 2;
    const int tid  = threadIdx.x;
    const int lane = tid & 31;
    const int warp = tid >> 5;
    const int wm   = warp >> 2;
    const int wn   = warp & 3;
    const int g    = lane >> 2;
    const int tg   = lane & 3;

    const int ar = tid >> 3, ac = (tid & 7) * 8;
    const int br = tid >> 4, bc = tid & 15;

    auto issue = [&](int kt, int buf) {
        __half* Ad = Ah + buf * 128 * 72;
        #pragma unroll
        for (int j = 0; j < 4; j++) {
            int r = ar + j * 32;
            cpa16(Ad + (size_t)r * 72 + ac,
                  Xh + (size_t)(m0 + r) * E_ + kt * 64 + ac);
        }
        __half* Bd = Bh + buf * 64 * 136;
        #pragma unroll
        for (int j = 0; j < 4; j++) {
            int r = br + j * 16;
            int h = h0 + (bc >> 3);
            int d = (bc & 7) * 8;
            cpa16(Bd + (size_t)r * 136 + bc * 8,
                  Wz + ((size_t)h * E_ + kt * 64 + r) * D_ + d);
        }
    };

    issue(0, 0); CP_COMMIT();
    issue(1, 1); CP_COMMIT();
    CP_WAIT(1);
    __syncthreads();

    float acc[4][4][4] = {};

    for (int kt = 0; kt < 16; kt++) {
        const int buf = kt % 3;
        const __half* At = Ah + buf * 128 * 72;
        const __half* Bt = Bh + buf * 64 * 136;
        #pragma unroll
        for (int ks = 0; ks < 4; ks++) {
            uint32_t a[4][4], b[8];
            #pragma unroll
            for (int mf = 0; mf < 4; mf++)
                ldsmA16(a[mf], At, wm * 64 + mf * 16, ks * 16, lane, 72);
            ldsmBt16(&b[0], Bt, wn * 32 + 0,  ks * 16, lane, 136);
            ldsmBt16(&b[4], Bt, wn * 32 + 16, ks * 16, lane, 136);
            #pragma unroll
            for (int mf = 0; mf < 4; mf++)
                #pragma unroll
                for (int nf = 0; nf < 4; nf++)
                    mma16(acc[mf][nf], a[mf], &b[nf * 2]);
        }
        CP_WAIT(0);          // kt+1 tile landed
        __syncthreads();     // publish kt+1; all warps done reading kt-1's buffer
        if (kt + 2 < 16) { issue(kt + 2, (kt + 2) % 3); CP_COMMIT(); }
    }

    // epilogue
    #pragma unroll
    for (int mf = 0; mf < 4; mf++) {
        #pragma unroll
        for (int hh = 0; hh < 2; hh++) {
            int m  = m0 + wm * 64 + mf * 16 + g + hh * 8;
            int bb = m >> 11;
            int t  = m & (T_ - 1);
            #pragma unroll
            for (int nf = 0; nf < 4; nf++) {
                int nn = wn * 32 + nf * 8 + 2 * tg;
                int h  = h0 + (nn >> 6);
                int d  = nn & 63;
                float v0 = (acc[mf][nf][hh * 2 + 0] + bias[h * D_ + d]) * osc;
                float v1 = (acc[mf][nf][hh * 2 + 1] + bias[h * D_ + d + 1]) * osc;
                *reinterpret_cast<__half2*>(
                    out + (((size_t)bb * H_ + h) * T_ + t) * D_ + d) =
                    __floats2half2_rn(v0, v1);
            }
        }
    }
}

// ---------------------------------------------------------------------------
// Pass A: column softmax stats. Q pre-scaled (acc already log2-domain).
// Warp-local (m,z) + cross-warp merge. ONE barrier per t-tile.
// grid (s_tile=16, bh=32), block 256, 8 warps of 64t x 32s.
// ---------------------------------------------------------------------------
__global__ __launch_bounds__(256) void stats_kernel(const __half* __restrict__ Q,
                                                    const __half* __restrict__ K,
                                                    float* __restrict__ cs_out)
{
    extern __shared__ __align__(16) __half sm[];
    __half* Ks = sm;                     // [128*72]
    __half* Qs = sm + 128 * 72;          // [3][128*72]
    float* redm = reinterpret_cast<float*>(sm + 4 * 128 * 72);   // [2][256]
    float* redz = redm + 512;                                    // [2][256]
    float* mrun = redz + 512;                                    // [128]
    float* zrun = mrun + 128;                                    // [128]

    const int st   = blockIdx.x;
    const int bh   = blockIdx.y;
    const int tid  = threadIdx.x;
    const int lane = tid & 31;
    const int warp = tid >> 5;
    const int wm   = warp >> 2;
    const int wn   = warp & 3;
    const int tg   = lane & 3;

    const int fr = tid >> 3, fc = (tid & 7) * 8;

    auto issueQ = [&](int it, int buf) {
        __half* Qd = Qs + buf * 128 * 72;
        const __half* Qp = Q + ((size_t)bh * T_ + it * 128) * D_;
        #pragma unroll
        for (int j = 0; j < 4; j++) {
            int r = fr + j * 32;
            cpa16(Qd + (size_t)r * 72 + fc, Qp + (size_t)r * D_ + fc);
        }
    };

    {
        const __half* Kp = K + ((size_t)bh * T_ + st * 128) * D_;
        #pragma unroll
        for (int j = 0; j < 4; j++) {
            int r = fr + j * 32;
            cpa16(Ks + (size_t)r * 72 + fc, Kp + (size_t)r * D_ + fc);
        }
        issueQ(st, st % 3);
        CP_COMMIT();
        int n1 = (st + 1 < 16) ? st + 1 : st;
        issueQ(n1, (st + 1) % 3);
        CP_COMMIT();
    }
    if (tid < 128) { mrun[tid] = -3.0e38f; zrun[tid] = 0.f; }
    CP_WAIT(1);
    __syncthreads();

    for (int it = st; it < 16; it++) {
        const __half* Qt = Qs + (it % 3) * 128 * 72;
        const int par = it & 1;

        float acc[4][4][4] = {};
        #pragma unroll
        for (int ks = 0; ks < 4; ks++) {
            uint32_t a[4][4], b[8];
            #pragma unroll
            for (int mf = 0; mf < 4; mf++)
                ldsmA16(a[mf], Qt, wm * 64 + mf * 16, ks * 16, lane, 72);
            ldsmBn16(&b[0], Ks, wn * 32 + 0,  ks * 16, lane, 72);
            ldsmBn16(&b[4], Ks, wn * 32 + 16, ks * 16, lane, 72);
            #pragma unroll
            for (int mf = 0; mf < 4; mf++)
                #pragma unroll
                for (int nf = 0; nf < 4; nf++)
                    mma16(acc[mf][nf], a[mf], &b[nf * 2]);
        }

        // causal mask (diag tile only; values already log2-domain)
        if (it == st) {
            #pragma unroll
            for (int mf = 0; mf < 4; mf++)
                #pragma unroll
                for (int hh = 0; hh < 2; hh++) {
                    int tl = wm * 64 + mf * 16 + (lane >> 2) + hh * 8;
                    #pragma unroll
                    for (int nf = 0; nf < 4; nf++)
                        #pragma unroll
                        for (int ci = 0; ci < 2; ci++) {
                            int sl = wn * 32 + nf * 8 + 2 * tg + ci;
                            if (tl < sl) acc[mf][nf][hh * 2 + ci] = -3.0e38f;
                        }
                }
        }

        // warp-local column max + exp-sum (shfl over g only)
        #pragma unroll
        for (int nf = 0; nf < 4; nf++)
            #pragma unroll
            for (int ci = 0; ci < 2; ci++) {
                float v = -3.0e38f;
                #pragma unroll
                for (int mf = 0; mf < 4; mf++) {
                    v = fmaxf(v, acc[mf][nf][ci]);
                    v = fmaxf(v, acc[mf][nf][2 + ci]);
                }
                v = fmaxf(v, __shfl_xor_sync(0xffffffffu, v, 4));
                v = fmaxf(v, __shfl_xor_sync(0xffffffffu, v, 8));
                v = fmaxf(v, __shfl_xor_sync(0xffffffffu, v, 16));
                float zs = 0.f;
                #pragma unroll
                for (int mf = 0; mf < 4; mf++) {
                    zs += fex2(acc[mf][nf][ci] - v);
                    zs += fex2(acc[mf][nf][2 + ci] - v);
                }
                zs += __shfl_xor_sync(0xffffffffu, zs, 4);
                zs += __shfl_xor_sync(0xffffffffu, zs, 8);
                zs += __shfl_xor_sync(0xffffffffu, zs, 16);
                if (lane < 4) {
                    int col = wn * 32 + nf * 8 + 2 * tg + ci;
                    redm[par * 256 + wm * 128 + col] = v;
                    redz[par * 256 + wm * 128 + col] = zs;
                }
            }

        CP_WAIT(0);          // Q(it+1) landed
        __syncthreads();     // publish red[par] + Q(it+1)

        if (tid < 128) {
            float m0 = redm[par * 256 + tid],      m1 = redm[par * 256 + 128 + tid];
            float z0 = redz[par * 256 + tid],      z1 = redz[par * 256 + 128 + tid];
            float mt = fmaxf(m0, m1);
            float zt = z0 * fex2(m0 - mt) + z1 * fex2(m1 - mt);
            float mo = mrun[tid];
            float mn = fmaxf(mo, mt);
            zrun[tid] = zrun[tid] * fex2(mo - mn) + zt * fex2(mt - mn);
            mrun[tid] = mn;
        }
        if (it + 2 < 16) { issueQ(it + 2, (it + 2) % 3); CP_COMMIT(); }
    }

    if (tid < 128) {
        int s = st * 128 + tid;
        cs_out[bh * T_ + s] = fex2(-mrun[tid]) / zrun[tid];
    }
}

// ---------------------------------------------------------------------------
// Pass B: out = P @ V, p = exp2(qk') * cs[s] (qk' pre-scaled).
// grid (t_tile=16 reversed, bh=32), block 256, 8 warps of 32t x 32n.
// Persistent Q fragments; triple-buffered K/V; double-buffered P;
// ONE barrier per chunk.
// ---------------------------------------------------------------------------
__global__ __launch_bounds__(256) void out_kernel(const __half* __restrict__ Q,
                                                  const __half* __restrict__ K,
                                                  const __half* __restrict__ V,
                                                  const float* __restrict__ cs_g,
                                                  float* __restrict__ out)
{
    extern __shared__ __align__(16) __half sm[];
    __half* Qs  = sm;                          // [128*72]
    __half* Ps  = sm + 128 * 72;               // [2][128*72]
    __half* Ksm = sm + 3 * 128 * 72;           // [3][64*72]
    __half* Vsm = Ksm + 3 * 64 * 72;           // [3][64*72]
    float*  cs  = reinterpret_cast<float*>(Vsm + 3 * 64 * 72);   // [3][64]

    const int tt   = (T_ / 128 - 1) - blockIdx.x;
    const int bh   = blockIdx.y;
    const int bb   = bh >> 4;
    const int h    = bh & 15;
    const int tid  = threadIdx.x;
    const int lane = tid & 31;
    const int warp = tid >> 5;
    const int g    = lane >> 2;
    const int tg   = lane & 3;

    const int wm = warp & 3;      // 32-row t group
    const int wn = warp >> 2;     // 32-col group (s for QK, d for PV)

    const int t0  = tt * 128;
    const int nch = 2 * tt + 2;

    const int fr = tid >> 3, fc = (tid & 7) * 8;

    const __half* Kb = K + (size_t)bh * T_ * D_;
    const __half* Vb = V + (size_t)bh * T_ * D_;

    auto issueKV = [&](int ic, int buf) {
        const __half* Kp = Kb + (size_t)ic * 64 * D_;
        const __half* Vp = Vb + (size_t)ic * 64 * D_;
        __half* Kd = Ksm + buf * 64 * 72;
        __half* Vd = Vsm + buf * 64 * 72;
        #pragma unroll
        for (int j = 0; j < 2; j++) {
            int r = fr + j * 32;
            cpa16(Kd + (size_t)r * 72 + fc, Kp + (size_t)r * D_ + fc);
            cpa16(Vd + (size_t)r * 72 + fc, Vp + (size_t)r * D_ + fc);
        }
        if (tid < 64) cpa4(cs + buf * 64 + tid, cs_g + (size_t)bh * T_ + ic * 64 + tid);
    };

    // prologue: Q tile + chunks 0,1
    {
        const __half* Qp = Q + ((size_t)bh * T_ + t0) * D_;
        #pragma unroll
        for (int j = 0; j < 4; j++) {
            int r = fr + j * 32;
            cpa16(Qs + (size_t)r * 72 + fc, Qp + (size_t)r * D_ + fc);
        }
        issueKV(0, 0); CP_COMMIT();
        issueKV(1, 1); CP_COMMIT();
    }
    CP_WAIT(1);          // Q + chunk0 done
    __syncthreads();

    // persistent Q fragments (warp rows wm*32..wm*32+31, full k=64)
    uint32_t aq[4][2][4];
    #pragma unroll
    for (int ks = 0; ks < 4; ks++)
        #pragma unroll
        for (int mf = 0; mf < 2; mf++)
            ldsmA16(aq[ks][mf], Qs, wm * 32 + mf * 16, ks * 16, lane, 72);

    float oacc[2][4][4] = {};

    for (int ic = 0; ic < nch; ic++) {
        const int s0  = ic * 64;
        const int kb3 = ic % 3;
        const __half* Kt = Ksm + kb3 * 64 * 72;
        const __half* Vt = Vsm + kb3 * 64 * 72;
        const float*  cb = cs + kb3 * 64;
        __half* Pd = Ps + (ic & 1) * 128 * 72;

        // QK chunk: warp 32t x 32s (A frags persistent)
        float sacc[2][4][4] = {};
        #pragma unroll
        for (int ks = 0; ks < 4; ks++) {
            uint32_t b[8];
            ldsmBn16(&b[0], Kt, wn * 32 + 0,  ks * 16, lane, 72);
            ldsmBn16(&b[4], Kt, wn * 32 + 16, ks * 16, lane, 72);
            #pragma unroll
            for (int mf = 0; mf < 2; mf++)
                #pragma unroll
                for (int nf = 0; nf < 4; nf++)
                    mma16(sacc[mf][nf], aq[ks][mf], &b[nf * 2]);
        }

        // p = exp2(qk') * cs[s]; causal mask on diag chunks; stage fp16 P
        const bool needmask = (s0 + 63 > t0);
        #pragma unroll
        for (int mf = 0; mf < 2; mf++)
            #pragma unroll
            for (int hh = 0; hh < 2; hh++) {
                int tl = wm * 32 + mf * 16 + g + hh * 8;
                #pragma unroll
                for (int nf = 0; nf < 4; nf++) {
                    int sl = wn * 32 + nf * 8 + 2 * tg;
                    float p0 = fex2(sacc[mf][nf][hh * 2 + 0]) * cb[sl];
                    float p1 = fex2(sacc[mf][nf][hh * 2 + 1]) * cb[sl + 1];
                    if (needmask) {
                        if (s0 + sl > t0 + tl)     p0 = 0.f;
                        if (s0 + sl + 1 > t0 + tl) p1 = 0.f;
                    }
                    *reinterpret_cast<__half2*>(Pd + (size_t)tl * 72 + sl) =
                        __floats2half2_rn(p0, p1);
                }
            }

        CP_WAIT(0);          // chunk ic+1 KV landed
        __syncthreads();     // publish P(ic) + KV(ic+1); all done with KV(ic-1)

        // PV: warp 32t x 32d over k=64
        #pragma unroll
        for (int ks = 0; ks < 4; ks++) {
            uint32_t a[2][4], b[8];
            #pragma unroll
            for (int mf = 0; mf < 2; mf++)
                ldsmA16(a[mf], Pd, wm * 32 + mf * 16, ks * 16, lane, 72);
            ldsmBt16(&b[0], Vt, wn * 32 + 0,  ks * 16, lane, 72);
            ldsmBt16(&b[4], Vt, wn * 32 + 16, ks * 16, lane, 72);
            #pragma unroll
            for (int mf = 0; mf < 2; mf++)
                #pragma unroll
                for (int nf = 0; nf < 4; nf++)
                    mma16(oacc[mf][nf], a[mf], &b[nf * 2]);
        }

        if (ic + 2 < nch) { issueKV(ic + 2, (ic + 2) % 3); CP_COMMIT(); }
    }

    // epilogue: (B,T,H,D) head-major concat
    #pragma unroll
    for (int mf = 0; mf < 2; mf++)
        #pragma unroll
        for (int hh = 0; hh < 2; hh++) {
            int t = t0 + wm * 32 + mf * 16 + g + hh * 8;
            #pragma unroll
            for (int nf = 0; nf < 4; nf++) {
                int d = wn * 32 + nf * 8 + 2 * tg;
                float2 val;
                val.x = oacc[mf][nf][hh * 2 + 0];
                val.y = oacc[mf][nf][hh * 2 + 1];
                *reinterpret_cast<float2*>(
                    out + (((size_t)bb * T_ + t) * H_ + h) * D_ + d) = val;
            }
        }
}

// ---------------------------------------------------------------------------
// Launch
// ---------------------------------------------------------------------------
extern "C" void kernel_launch(void* const* d_in, const int* in_sizes, int n_in,
                              void* d_out, int out_size)
{
    const float* X   = (const float*)d_in[0];
    const float* k_w = (const float*)d_in[1];
    const float* k_b = (const float*)d_in[2];
    const float* q_w = (const float*)d_in[3];
    const float* q_b = (const float*)d_in[4];
    const float* v_w = (const float*)d_in[5];
    const float* v_b = (const float*)d_in[6];
    float* out = (float*)d_out;

    __half *pxh, *pwh, *pq, *pk, *pv;
    float* pcs;
    cudaGetSymbolAddress((void**)&pxh, g_xh);
    cudaGetSymbolAddress((void**)&pwh, g_wh);
    cudaGetSymbolAddress((void**)&pq, g_q);
    cudaGetSymbolAddress((void**)&pk, g_k);
    cudaGetSymbolAddress((void**)&pv, g_v);
    cudaGetSymbolAddress((void**)&pcs, g_cs);

    const int SP = 3 * (128 * 72 + 64 * 136) * 2;                         // 107520
    const int SA = 4 * 128 * 72 * 2 + (512 + 512 + 128 + 128) * 4;        // 78848
    const int SB = (3 * 128 * 72 + 6 * 64 * 72) * 2 + 3 * 64 * 4;         // 111360

    cudaFuncSetAttribute(proj_kernel,  cudaFuncAttributeMaxDynamicSharedMemorySize, SP);
    cudaFuncSetAttribute(stats_kernel, cudaFuncAttributeMaxDynamicSharedMemorySize, SA);
    cudaFuncSetAttribute(out_kernel,   cudaFuncAttributeMaxDynamicSharedMemorySize, SB);

    prep_kernel<<<7168, 256>>>(X, q_w, k_w, v_w, pxh, pwh);

    dim3 projGrid(B_ * T_ / 128, H_ / 2, 3);
    proj_kernel<<<projGrid, 256, SP>>>(pxh, pwh, q_b, k_b, v_b, pq, pk, pv);

    dim3 stGrid(T_ / 128, BH_);
    stats_kernel<<<stGrid, 256, SA>>>(pq, pk, pcs);

    dim3 outGrid(T_ / 128, BH_);
    out_kernel<<<outGrid, 256, SB>>>(pq, pk, pv, pcs, out);
}

// round 11
// speedup vs baseline: 2.6851x; 1.0465x over previous
#include <cuda_runtime.h>
#include <cuda_fp16.h>
#include <cstdint>

#define B_  2
#define T_  2048
#define E_  1024
#define H_  16
#define D_  64
#define BH_ (B_*H_)       // 32

// scale * log2(e): softmax computed in base-2 domain (folded into Q at proj)
#define KS2 0.18033688011112042592f

// ---------------------------------------------------------------------------
// Device scratch
// ---------------------------------------------------------------------------
__device__ __half g_xh[(size_t)B_ * T_ * E_];
__device__ __half g_wh[(size_t)3 * H_ * E_ * D_];
__device__ __half g_q[(size_t)BH_ * T_ * D_];      // pre-scaled by KS2
__device__ __half g_k[(size_t)BH_ * T_ * D_];
__device__ __half g_v[(size_t)BH_ * T_ * D_];
__device__ float  g_cs[(size_t)BH_ * T_];          // exp2(-m)/z

// ---------------------------------------------------------------------------
// helpers
// ---------------------------------------------------------------------------
__device__ __forceinline__ float fex2(float x) {
    float r;
    asm("ex2.approx.f32 %0, %1;" : "=f"(r) : "f"(x));
    return r;
}

__device__ __forceinline__ void mma16(float* c, const uint32_t* a, const uint32_t* b) {
    asm("mma.sync.aligned.m16n8k16.row.col.f32.f16.f16.f32 "
        "{%0,%1,%2,%3},{%4,%5,%6,%7},{%8,%9},{%0,%1,%2,%3};"
        : "+f"(c[0]), "+f"(c[1]), "+f"(c[2]), "+f"(c[3])
        : "r"(a[0]), "r"(a[1]), "r"(a[2]), "r"(a[3]), "r"(b[0]), "r"(b[1]));
}

__device__ __forceinline__ void ldsmA16(uint32_t* r, const __half* base,
                                        int row0, int k0, int lane, int S) {
    const __half* p = base + (size_t)(row0 + (lane & 7) + ((lane >> 3) & 1) * 8) * S
                      + k0 + (lane >> 4) * 8;
    uint32_t a = (uint32_t)__cvta_generic_to_shared(p);
    asm volatile("ldmatrix.sync.aligned.m8n8.x4.shared.b16 {%0,%1,%2,%3}, [%4];"
                 : "=r"(r[0]), "=r"(r[1]), "=r"(r[2]), "=r"(r[3]) : "r"(a));
}

__device__ __forceinline__ void ldsmBn16(uint32_t* r, const __half* base,
                                         int n0, int k0, int lane, int S) {
    const __half* p = base + (size_t)(n0 + (lane & 7) + (lane >> 4) * 8) * S
                      + k0 + ((lane >> 3) & 1) * 8;
    uint32_t a = (uint32_t)__cvta_generic_to_shared(p);
    asm volatile("ldmatrix.sync.aligned.m8n8.x4.shared.b16 {%0,%1,%2,%3}, [%4];"
                 : "=r"(r[0]), "=r"(r[1]), "=r"(r[2]), "=r"(r[3]) : "r"(a));
}

__device__ __forceinline__ void ldsmBt16(uint32_t* r, const __half* base,
                                         int n0, int k0, int lane, int S) {
    const __half* p = base + (size_t)(k0 + (lane & 7) + ((lane >> 3) & 1) * 8) * S
                      + n0 + (lane >> 4) * 8;
    uint32_t a = (uint32_t)__cvta_generic_to_shared(p);
    asm volatile("ldmatrix.sync.aligned.m8n8.x4.trans.shared.b16 {%0,%1,%2,%3}, [%4];"
                 : "=r"(r[0]), "=r"(r[1]), "=r"(r[2]), "=r"(r[3]) : "r"(a));
}

__device__ __forceinline__ void cpa16(void* smem_ptr, const void* g) {
    uint32_t a = (uint32_t)__cvta_generic_to_shared(smem_ptr);
    asm volatile("cp.async.cg.shared.global [%0], [%1], 16;" :: "r"(a), "l"(g));
}
__device__ __forceinline__ void cpa4(void* smem_ptr, const void* g) {
    uint32_t a = (uint32_t)__cvta_generic_to_shared(smem_ptr);
    asm volatile("cp.async.ca.shared.global [%0], [%1], 4;" :: "r"(a), "l"(g));
}
#define CP_COMMIT() asm volatile("cp.async.commit_group;" ::: "memory")
#define CP_WAIT(N)  asm volatile("cp.async.wait_group " #N ";" ::: "memory")

// ---------------------------------------------------------------------------
// Kernel 0: convert X and W to fp16 scratch.
// ---------------------------------------------------------------------------
__global__ __launch_bounds__(256) void prep_kernel(const float* __restrict__ X,
                                                   const float* __restrict__ qw,
                                                   const float* __restrict__ kw,
                                                   const float* __restrict__ vw,
                                                   __half* __restrict__ Xh,
                                                   __half* __restrict__ Wh)
{
    const size_t XN4 = (size_t)B_ * T_ * E_ / 4;
    size_t i4 = (size_t)blockIdx.x * 256 + threadIdx.x;
    float4 v;
    uint2* dst;
    if (i4 < XN4) {
        v = reinterpret_cast<const float4*>(X)[i4];
        dst = reinterpret_cast<uint2*>(Xh) + i4;
    } else {
        size_t j = i4 - XN4;
        size_t base = j * 4;
        int z = (int)(base >> 20);
        size_t rem = base & ((1u << 20) - 1);
        const float* W = (z == 0) ? qw : (z == 1) ? kw : vw;
        v = *reinterpret_cast<const float4*>(W + rem);
        dst = reinterpret_cast<uint2*>(Wh) + j;
    }
    __half2 lo = __floats2half2_rn(v.x, v.y);
    __half2 hi = __floats2half2_rn(v.z, v.w);
    uint2 u;
    u.x = *reinterpret_cast<uint32_t*>(&lo);
    u.y = *reinterpret_cast<uint32_t*>(&hi);
    *dst = u;
}

// ---------------------------------------------------------------------------
// Kernel 1: fused QKV projection. 128m x 128n block, 8 warps of 64x32.
// Triple-buffered cp.async, ONE barrier per K-tile. Q output scaled by KS2.
// ---------------------------------------------------------------------------
__global__ __launch_bounds__(256, 2) void proj_kernel(const __half* __restrict__ Xh,
                                                      const __half* __restrict__ Wh,
                                                      const float* __restrict__ qb,
                                                      const float* __restrict__ kb,
                                                      const float* __restrict__ vb,
                                                      __half* __restrict__ oq,
                                                      __half* __restrict__ ok,
                                                      __half* __restrict__ ov)
{
    extern __shared__ __align__(16) __half sm[];
    __half* Ah = sm;                     // [3][128*72]
    __half* Bh = sm + 3 * 128 * 72;      // [3][64*136]

    const int z = blockIdx.z;
    const float* bias = (z == 0) ? qb : (z == 1) ? kb : vb;
    __half* out = (z == 0) ? oq : (z == 1) ? ok : ov;
    const float osc = (z == 0) ? KS2 : 1.0f;
    const __half* Wz = Wh + (size_t)z * H_ * E_ * D_;

    const int m0   = blockIdx.x * 128;
    const int h0   = blockIdx.y * 2;
    const int tid  = threadIdx.x;
    const int lane = tid & 31;
    const int warp = tid >> 5;
    const int wm   = warp >> 2;
    const int wn   = warp & 3;
    const int g    = lane >> 2;
    const int tg   = lane & 3;

    const int ar = tid >> 3, ac = (tid & 7) * 8;
    const int br = tid >> 4, bc = tid & 15;

    auto issue = [&](int kt, int buf) {
        __half* Ad = Ah + buf * 128 * 72;
        #pragma unroll
        for (int j = 0; j < 4; j++) {
            int r = ar + j * 32;
            cpa16(Ad + (size_t)r * 72 + ac,
                  Xh + (size_t)(m0 + r) * E_ + kt * 64 + ac);
        }
        __half* Bd = Bh + buf * 64 * 136;
        #pragma unroll
        for (int j = 0; j < 4; j++) {
            int r = br + j * 16;
            int h = h0 + (bc >> 3);
            int d = (bc & 7) * 8;
            cpa16(Bd + (size_t)r * 136 + bc * 8,
                  Wz + ((size_t)h * E_ + kt * 64 + r) * D_ + d);
        }
    };

    issue(0, 0); CP_COMMIT();
    issue(1, 1); CP_COMMIT();
    CP_WAIT(1);
    __syncthreads();

    float acc[4][4][4] = {};

    for (int kt = 0; kt < 16; kt++) {
        const int buf = kt % 3;
        const __half* At = Ah + buf * 128 * 72;
        const __half* Bt = Bh + buf * 64 * 136;
        #pragma unroll
        for (int ks = 0; ks < 4; ks++) {
            uint32_t a[4][4], b[8];
            #pragma unroll
            for (int mf = 0; mf < 4; mf++)
                ldsmA16(a[mf], At, wm * 64 + mf * 16, ks * 16, lane, 72);
            ldsmBt16(&b[0], Bt, wn * 32 + 0,  ks * 16, lane, 136);
            ldsmBt16(&b[4], Bt, wn * 32 + 16, ks * 16, lane, 136);
            #pragma unroll
            for (int mf = 0; mf < 4; mf++)
                #pragma unroll
                for (int nf = 0; nf < 4; nf++)
                    mma16(acc[mf][nf], a[mf], &b[nf * 2]);
        }
        CP_WAIT(0);
        __syncthreads();
        if (kt + 2 < 16) { issue(kt + 2, (kt + 2) % 3); CP_COMMIT(); }
    }

    // epilogue
    #pragma unroll
    for (int mf = 0; mf < 4; mf++) {
        #pragma unroll
        for (int hh = 0; hh < 2; hh++) {
            int m  = m0 + wm * 64 + mf * 16 + g + hh * 8;
            int bb = m >> 11;
            int t  = m & (T_ - 1);
            #pragma unroll
            for (int nf = 0; nf < 4; nf++) {
                int nn = wn * 32 + nf * 8 + 2 * tg;
                int h  = h0 + (nn >> 6);
                int d  = nn & 63;
                float v0 = (acc[mf][nf][hh * 2 + 0] + bias[h * D_ + d]) * osc;
                float v1 = (acc[mf][nf][hh * 2 + 1] + bias[h * D_ + d + 1]) * osc;
                *reinterpret_cast<__half2*>(
                    out + (((size_t)bb * H_ + h) * T_ + t) * D_ + d) =
                    __floats2half2_rn(v0, v1);
            }
        }
    }
}

// ---------------------------------------------------------------------------
// Pass A: column softmax stats. Q pre-scaled (acc already log2-domain).
// Warp-local (m,z) + cross-warp merge. ONE barrier per t-tile.
// grid (s_tile=16, bh=32), block 256, 8 warps of 64t x 32s.
// ---------------------------------------------------------------------------
__global__ __launch_bounds__(256) void stats_kernel(const __half* __restrict__ Q,
                                                    const __half* __restrict__ K,
                                                    float* __restrict__ cs_out)
{
    extern __shared__ __align__(16) __half sm[];
    __half* Ks = sm;                     // [128*72]
    __half* Qs = sm + 128 * 72;          // [3][128*72]
    float* redm = reinterpret_cast<float*>(sm + 4 * 128 * 72);   // [2][256]
    float* redz = redm + 512;                                    // [2][256]
    float* mrun = redz + 512;                                    // [128]
    float* zrun = mrun + 128;                                    // [128]

    const int st   = blockIdx.x;
    const int bh   = blockIdx.y;
    const int tid  = threadIdx.x;
    const int lane = tid & 31;
    const int warp = tid >> 5;
    const int wm   = warp >> 2;
    const int wn   = warp & 3;
    const int tg   = lane & 3;

    const int fr = tid >> 3, fc = (tid & 7) * 8;

    auto issueQ = [&](int it, int buf) {
        __half* Qd = Qs + buf * 128 * 72;
        const __half* Qp = Q + ((size_t)bh * T_ + it * 128) * D_;
        #pragma unroll
        for (int j = 0; j < 4; j++) {
            int r = fr + j * 32;
            cpa16(Qd + (size_t)r * 72 + fc, Qp + (size_t)r * D_ + fc);
        }
    };

    {
        const __half* Kp = K + ((size_t)bh * T_ + st * 128) * D_;
        #pragma unroll
        for (int j = 0; j < 4; j++) {
            int r = fr + j * 32;
            cpa16(Ks + (size_t)r * 72 + fc, Kp + (size_t)r * D_ + fc);
        }
        issueQ(st, st % 3);
        CP_COMMIT();
        int n1 = (st + 1 < 16) ? st + 1 : st;
        issueQ(n1, (st + 1) % 3);
        CP_COMMIT();
    }
    if (tid < 128) { mrun[tid] = -3.0e38f; zrun[tid] = 0.f; }
    CP_WAIT(1);
    __syncthreads();

    for (int it = st; it < 16; it++) {
        const __half* Qt = Qs + (it % 3) * 128 * 72;
        const int par = it & 1;

        float acc[4][4][4] = {};
        #pragma unroll
        for (int ks = 0; ks < 4; ks++) {
            uint32_t a[4][4], b[8];
            #pragma unroll
            for (int mf = 0; mf < 4; mf++)
                ldsmA16(a[mf], Qt, wm * 64 + mf * 16, ks * 16, lane, 72);
            ldsmBn16(&b[0], Ks, wn * 32 + 0,  ks * 16, lane, 72);
            ldsmBn16(&b[4], Ks, wn * 32 + 16, ks * 16, lane, 72);
            #pragma unroll
            for (int mf = 0; mf < 4; mf++)
                #pragma unroll
                for (int nf = 0; nf < 4; nf++)
                    mma16(acc[mf][nf], a[mf], &b[nf * 2]);
        }

        // causal mask (diag tile only; values already log2-domain)
        if (it == st) {
            #pragma unroll
            for (int mf = 0; mf < 4; mf++)
                #pragma unroll
                for (int hh = 0; hh < 2; hh++) {
                    int tl = wm * 64 + mf * 16 + (lane >> 2) + hh * 8;
                    #pragma unroll
                    for (int nf = 0; nf < 4; nf++)
                        #pragma unroll
                        for (int ci = 0; ci < 2; ci++) {
                            int sl = wn * 32 + nf * 8 + 2 * tg + ci;
                            if (tl < sl) acc[mf][nf][hh * 2 + ci] = -3.0e38f;
                        }
                }
        }

        // warp-local column max + exp-sum
        #pragma unroll
        for (int nf = 0; nf < 4; nf++)
            #pragma unroll
            for (int ci = 0; ci < 2; ci++) {
                float v = -3.0e38f;
                #pragma unroll
                for (int mf = 0; mf < 4; mf++) {
                    v = fmaxf(v, acc[mf][nf][ci]);
                    v = fmaxf(v, acc[mf][nf][2 + ci]);
                }
                v = fmaxf(v, __shfl_xor_sync(0xffffffffu, v, 4));
                v = fmaxf(v, __shfl_xor_sync(0xffffffffu, v, 8));
                v = fmaxf(v, __shfl_xor_sync(0xffffffffu, v, 16));
                float zs = 0.f;
                #pragma unroll
                for (int mf = 0; mf < 4; mf++) {
                    zs += fex2(acc[mf][nf][ci] - v);
                    zs += fex2(acc[mf][nf][2 + ci] - v);
                }
                zs += __shfl_xor_sync(0xffffffffu, zs, 4);
                zs += __shfl_xor_sync(0xffffffffu, zs, 8);
                zs += __shfl_xor_sync(0xffffffffu, zs, 16);
                if (lane < 4) {
                    int col = wn * 32 + nf * 8 + 2 * tg + ci;
                    redm[par * 256 + wm * 128 + col] = v;
                    redz[par * 256 + wm * 128 + col] = zs;
                }
            }

        CP_WAIT(0);
        __syncthreads();

        if (tid < 128) {
            float m0 = redm[par * 256 + tid],      m1 = redm[par * 256 + 128 + tid];
            float z0 = redz[par * 256 + tid],      z1 = redz[par * 256 + 128 + tid];
            float mt = fmaxf(m0, m1);
            float zt = z0 * fex2(m0 - mt) + z1 * fex2(m1 - mt);
            float mo = mrun[tid];
            float mn = fmaxf(mo, mt);
            zrun[tid] = zrun[tid] * fex2(mo - mn) + zt * fex2(mt - mn);
            mrun[tid] = mn;
        }
        if (it + 2 < 16) { issueQ(it + 2, (it + 2) % 3); CP_COMMIT(); }
    }

    if (tid < 128) {
        int s = st * 128 + tid;
        cs_out[bh * T_ + s] = fex2(-mrun[tid]) / zrun[tid];
    }
}

// ---------------------------------------------------------------------------
// Pass B (FA2-style): out = P @ V with P register-resident.
// grid (t_tile=16 reversed, bh=32), block 256, 8 warps of 16t x 64s.
// QK C-fragment repacked directly as PV A-fragment (no P smem, no
// intra-chunk barrier). Triple-buffered K/V, ONE barrier per chunk.
// ---------------------------------------------------------------------------
__global__ __launch_bounds__(256, 2) void out_kernel(const __half* __restrict__ Q,
                                                     const __half* __restrict__ K,
                                                     const __half* __restrict__ V,
                                                     const float* __restrict__ cs_g,
                                                     float* __restrict__ out)
{
    extern __shared__ __align__(16) __half sm[];
    __half* Qs  = sm;                          // [128*72]
    __half* Ksm = sm + 128 * 72;               // [3][64*72]
    __half* Vsm = Ksm + 3 * 64 * 72;           // [3][64*72]
    float*  cs  = reinterpret_cast<float*>(Vsm + 3 * 64 * 72);   // [3][64]

    const int tt   = (T_ / 128 - 1) - blockIdx.x;
    const int bh   = blockIdx.y;
    const int bb   = bh >> 4;
    const int h    = bh & 15;
    const int tid  = threadIdx.x;
    const int lane = tid & 31;
    const int warp = tid >> 5;      // rows warp*16 .. warp*16+15
    const int g    = lane >> 2;
    const int tg   = lane & 3;

    const int t0  = tt * 128;
    const int nch = 2 * tt + 2;

    const int fr = tid >> 3, fc = (tid & 7) * 8;

    const __half* Kb = K + (size_t)bh * T_ * D_;
    const __half* Vb = V + (size_t)bh * T_ * D_;

    auto issueKV = [&](int ic, int buf) {
        const __half* Kp = Kb + (size_t)ic * 64 * D_;
        const __half* Vp = Vb + (size_t)ic * 64 * D_;
        __half* Kd = Ksm + buf * 64 * 72;
        __half* Vd = Vsm + buf * 64 * 72;
        #pragma unroll
        for (int j = 0; j < 2; j++) {
            int r = fr + j * 32;
            cpa16(Kd + (size_t)r * 72 + fc, Kp + (size_t)r * D_ + fc);
            cpa16(Vd + (size_t)r * 72 + fc, Vp + (size_t)r * D_ + fc);
        }
        if (tid < 64) cpa4(cs + buf * 64 + tid, cs_g + (size_t)bh * T_ + ic * 64 + tid);
    };

    // prologue: Q tile + chunk0 (group 0), chunk1 (group 1)
    {
        const __half* Qp = Q + ((size_t)bh * T_ + t0) * D_;
        #pragma unroll
        for (int j = 0; j < 4; j++) {
            int r = fr + j * 32;
            cpa16(Qs + (size_t)r * 72 + fc, Qp + (size_t)r * D_ + fc);
        }
        issueKV(0, 0); CP_COMMIT();
        issueKV(1, 1); CP_COMMIT();
    }
    CP_WAIT(1);          // Q + chunk0 done
    __syncthreads();

    // persistent Q fragments: 16 rows, full k=64 (4 k-groups)
    uint32_t aq[4][4];
    #pragma unroll
    for (int ks = 0; ks < 4; ks++)
        ldsmA16(aq[ks], Qs, warp * 16, ks * 16, lane, 72);

    float oacc[8][4] = {};

    for (int ic = 0; ic < nch; ic++) {
        CP_WAIT(1);          // chunk ic KV landed (newest pending = ic+1)
        __syncthreads();     // visibility + buffer-reuse protection
        if (ic + 2 < nch) { issueKV(ic + 2, (ic + 2) % 3); CP_COMMIT(); }

        const int s0  = ic * 64;
        const int b3  = ic % 3;
        const __half* Kt = Ksm + b3 * 64 * 72;
        const __half* Vt = Vsm + b3 * 64 * 72;
        const float*  cb = cs + b3 * 64;

        // QK: 16t x 64s, k=64 (Q frags persistent)
        float sacc[8][4] = {};
        #pragma unroll
        for (int ks = 0; ks < 4; ks++) {
            uint32_t bk[16];
            ldsmBn16(&bk[0],  Kt, 0,  ks * 16, lane, 72);
            ldsmBn16(&bk[4],  Kt, 16, ks * 16, lane, 72);
            ldsmBn16(&bk[8],  Kt, 32, ks * 16, lane, 72);
            ldsmBn16(&bk[12], Kt, 48, ks * 16, lane, 72);
            #pragma unroll
            for (int nf = 0; nf < 8; nf++)
                mma16(sacc[nf], aq[ks], &bk[nf * 2]);
        }

        // p = exp2(qk') * cs[s]; mask diag chunks; pack C->A frags in regs
        const bool needmask = (s0 + 63 > t0);
        const int tl0 = t0 + warp * 16 + g;
        const int tl1 = tl0 + 8;
        uint32_t pa[4][4];
        #pragma unroll
        for (int nf = 0; nf < 8; nf++) {
            int sl = nf * 8 + 2 * tg;
            float p0 = fex2(sacc[nf][0]) * cb[sl];
            float p1 = fex2(sacc[nf][1]) * cb[sl + 1];
            float p2 = fex2(sacc[nf][2]) * cb[sl];
            float p3 = fex2(sacc[nf][3]) * cb[sl + 1];
            if (needmask) {
                int sa = s0 + sl;
                if (sa > tl0)     p0 = 0.f;
                if (sa + 1 > tl0) p1 = 0.f;
                if (sa > tl1)     p2 = 0.f;
                if (sa + 1 > tl1) p3 = 0.f;
            }
            __half2 h01 = __floats2half2_rn(p0, p1);
            __half2 h23 = __floats2half2_rn(p2, p3);
            int kg = nf >> 1;
            int hi = (nf & 1) * 2;
            pa[kg][hi + 0] = *reinterpret_cast<uint32_t*>(&h01);
            pa[kg][hi + 1] = *reinterpret_cast<uint32_t*>(&h23);
        }

        // PV: 16t x 64d, k=64 (P in registers)
        #pragma unroll
        for (int kg = 0; kg < 4; kg++) {
            uint32_t bv[16];
            ldsmBt16(&bv[0],  Vt, 0,  kg * 16, lane, 72);
            ldsmBt16(&bv[4],  Vt, 16, kg * 16, lane, 72);
            ldsmBt16(&bv[8],  Vt, 32, kg * 16, lane, 72);
            ldsmBt16(&bv[12], Vt, 48, kg * 16, lane, 72);
            #pragma unroll
            for (int nf = 0; nf < 8; nf++)
                mma16(oacc[nf], pa[kg], &bv[nf * 2]);
        }
    }

    // epilogue: (B,T,H,D) head-major concat
    #pragma unroll
    for (int hh = 0; hh < 2; hh++) {
        int t = t0 + warp * 16 + g + hh * 8;
        #pragma unroll
        for (int nf = 0; nf < 8; nf++) {
            int d = nf * 8 + 2 * tg;
            float2 val;
            val.x = oacc[nf][hh * 2 + 0];
            val.y = oacc[nf][hh * 2 + 1];
            *reinterpret_cast<float2*>(
                out + (((size_t)bb * T_ + t) * H_ + h) * D_ + d) = val;
        }
    }
}

// ---------------------------------------------------------------------------
// Launch
// ---------------------------------------------------------------------------
extern "C" void kernel_launch(void* const* d_in, const int* in_sizes, int n_in,
                              void* d_out, int out_size)
{
    const float* X   = (const float*)d_in[0];
    const float* k_w = (const float*)d_in[1];
    const float* k_b = (const float*)d_in[2];
    const float* q_w = (const float*)d_in[3];
    const float* q_b = (const float*)d_in[4];
    const float* v_w = (const float*)d_in[5];
    const float* v_b = (const float*)d_in[6];
    float* out = (float*)d_out;

    __half *pxh, *pwh, *pq, *pk, *pv;
    float* pcs;
    cudaGetSymbolAddress((void**)&pxh, g_xh);
    cudaGetSymbolAddress((void**)&pwh, g_wh);
    cudaGetSymbolAddress((void**)&pq, g_q);
    cudaGetSymbolAddress((void**)&pk, g_k);
    cudaGetSymbolAddress((void**)&pv, g_v);
    cudaGetSymbolAddress((void**)&pcs, g_cs);

    const int SP = 3 * (128 * 72 + 64 * 136) * 2;                         // 107520
    const int SA = 4 * 128 * 72 * 2 + (512 + 512 + 128 + 128) * 4;        // 78848
    const int SB = (128 * 72 + 6 * 64 * 72) * 2 + 3 * 64 * 4;             // 74496

    cudaFuncSetAttribute(proj_kernel,  cudaFuncAttributeMaxDynamicSharedMemorySize, SP);
    cudaFuncSetAttribute(stats_kernel, cudaFuncAttributeMaxDynamicSharedMemorySize, SA);
    cudaFuncSetAttribute(out_kernel,   cudaFuncAttributeMaxDynamicSharedMemorySize, SB);

    prep_kernel<<<7168, 256>>>(X, q_w, k_w, v_w, pxh, pwh);

    dim3 projGrid(B_ * T_ / 128, H_ / 2, 3);
    proj_kernel<<<projGrid, 256, SP>>>(pxh, pwh, q_b, k_b, v_b, pq, pk, pv);

    dim3 stGrid(T_ / 128, BH_);
    stats_kernel<<<stGrid, 256, SA>>>(pq, pk, pcs);

    dim3 outGrid(T_ / 128, BH_);
    out_kernel<<<outGrid, 256, SB>>>(pq, pk, pv, pcs, out);
}

// round 12
// speedup vs baseline: 2.7355x; 1.0188x over previous
#include <cuda_runtime.h>
#include <cuda_fp16.h>
#include <cstdint>

#define B_  2
#define T_  2048
#define E_  1024
#define H_  16
#define D_  64
#define BH_ (B_*H_)       // 32

// scale * log2(e): softmax computed in base-2 domain (folded into Q at proj)
#define KS2 0.18033688011112042592f

// ---------------------------------------------------------------------------
// Device scratch
// ---------------------------------------------------------------------------
__device__ __half g_xh[(size_t)B_ * T_ * E_];
__device__ __half g_wh[(size_t)3 * H_ * E_ * D_];
__device__ __half g_q[(size_t)BH_ * T_ * D_];      // pre-scaled by KS2
__device__ __half g_k[(size_t)BH_ * T_ * D_];
__device__ __half g_v[(size_t)BH_ * T_ * D_];
__device__ float  g_cs[(size_t)BH_ * T_];          // lcs[s] = -m - log2(z)

// ---------------------------------------------------------------------------
// helpers
// ---------------------------------------------------------------------------
__device__ __forceinline__ float fex2(float x) {
    float r;
    asm("ex2.approx.f32 %0, %1;" : "=f"(r) : "f"(x));
    return r;
}

// pack two fp32 -> half2, then 2^x on both halves in ONE MUFU op.
__device__ __forceinline__ uint32_t ex2x2(float lo, float hi) {
    uint32_t h, r;
    asm("cvt.rn.f16x2.f32 %0, %1, %2;" : "=r"(h) : "f"(hi), "f"(lo));
    asm("ex2.approx.f16x2 %0, %1;" : "=r"(r) : "r"(h));
    return r;
}

__device__ __forceinline__ void mma16(float* c, const uint32_t* a, const uint32_t* b) {
    asm("mma.sync.aligned.m16n8k16.row.col.f32.f16.f16.f32 "
        "{%0,%1,%2,%3},{%4,%5,%6,%7},{%8,%9},{%0,%1,%2,%3};"
        : "+f"(c[0]), "+f"(c[1]), "+f"(c[2]), "+f"(c[3])
        : "r"(a[0]), "r"(a[1]), "r"(a[2]), "r"(a[3]), "r"(b[0]), "r"(b[1]));
}

__device__ __forceinline__ void ldsmA16(uint32_t* r, const __half* base,
                                        int row0, int k0, int lane, int S) {
    const __half* p = base + (size_t)(row0 + (lane & 7) + ((lane >> 3) & 1) * 8) * S
                      + k0 + (lane >> 4) * 8;
    uint32_t a = (uint32_t)__cvta_generic_to_shared(p);
    asm volatile("ldmatrix.sync.aligned.m8n8.x4.shared.b16 {%0,%1,%2,%3}, [%4];"
                 : "=r"(r[0]), "=r"(r[1]), "=r"(r[2]), "=r"(r[3]) : "r"(a));
}

__device__ __forceinline__ void ldsmBn16(uint32_t* r, const __half* base,
                                         int n0, int k0, int lane, int S) {
    const __half* p = base + (size_t)(n0 + (lane & 7) + (lane >> 4) * 8) * S
                      + k0 + ((lane >> 3) & 1) * 8;
    uint32_t a = (uint32_t)__cvta_generic_to_shared(p);
    asm volatile("ldmatrix.sync.aligned.m8n8.x4.shared.b16 {%0,%1,%2,%3}, [%4];"
                 : "=r"(r[0]), "=r"(r[1]), "=r"(r[2]), "=r"(r[3]) : "r"(a));
}

__device__ __forceinline__ void ldsmBt16(uint32_t* r, const __half* base,
                                         int n0, int k0, int lane, int S) {
    const __half* p = base + (size_t)(k0 + (lane & 7) + ((lane >> 3) & 1) * 8) * S
                      + n0 + (lane >> 4) * 8;
    uint32_t a = (uint32_t)__cvta_generic_to_shared(p);
    asm volatile("ldmatrix.sync.aligned.m8n8.x4.trans.shared.b16 {%0,%1,%2,%3}, [%4];"
                 : "=r"(r[0]), "=r"(r[1]), "=r"(r[2]), "=r"(r[3]) : "r"(a));
}

__device__ __forceinline__ void cpa16(void* smem_ptr, const void* g) {
    uint32_t a = (uint32_t)__cvta_generic_to_shared(smem_ptr);
    asm volatile("cp.async.cg.shared.global [%0], [%1], 16;" :: "r"(a), "l"(g));
}
__device__ __forceinline__ void cpa4(void* smem_ptr, const void* g) {
    uint32_t a = (uint32_t)__cvta_generic_to_shared(smem_ptr);
    asm volatile("cp.async.ca.shared.global [%0], [%1], 4;" :: "r"(a), "l"(g));
}
#define CP_COMMIT() asm volatile("cp.async.commit_group;" ::: "memory")
#define CP_WAIT(N)  asm volatile("cp.async.wait_group " #N ";" ::: "memory")

// ---------------------------------------------------------------------------
// Kernel 0: convert X and W to fp16 scratch.
// ---------------------------------------------------------------------------
__global__ __launch_bounds__(256) void prep_kernel(const float* __restrict__ X,
                                                   const float* __restrict__ qw,
                                                   const float* __restrict__ kw,
                                                   const float* __restrict__ vw,
                                                   __half* __restrict__ Xh,
                                                   __half* __restrict__ Wh)
{
    const size_t XN4 = (size_t)B_ * T_ * E_ / 4;
    size_t i4 = (size_t)blockIdx.x * 256 + threadIdx.x;
    float4 v;
    uint2* dst;
    if (i4 < XN4) {
        v = reinterpret_cast<const float4*>(X)[i4];
        dst = reinterpret_cast<uint2*>(Xh) + i4;
    } else {
        size_t j = i4 - XN4;
        size_t base = j * 4;
        int z = (int)(base >> 20);
        size_t rem = base & ((1u << 20) - 1);
        const float* W = (z == 0) ? qw : (z == 1) ? kw : vw;
        v = *reinterpret_cast<const float4*>(W + rem);
        dst = reinterpret_cast<uint2*>(Wh) + j;
    }
    __half2 lo = __floats2half2_rn(v.x, v.y);
    __half2 hi = __floats2half2_rn(v.z, v.w);
    uint2 u;
    u.x = *reinterpret_cast<uint32_t*>(&lo);
    u.y = *reinterpret_cast<uint32_t*>(&hi);
    *dst = u;
}

// ---------------------------------------------------------------------------
// Kernel 1: fused QKV projection. 128m x 128n block, 8 warps of 64x32.
// Triple-buffered cp.async, ONE barrier per K-tile. Q output scaled by KS2.
// ---------------------------------------------------------------------------
__global__ __launch_bounds__(256, 2) void proj_kernel(const __half* __restrict__ Xh,
                                                      const __half* __restrict__ Wh,
                                                      const float* __restrict__ qb,
                                                      const float* __restrict__ kb,
                                                      const float* __restrict__ vb,
                                                      __half* __restrict__ oq,
                                                      __half* __restrict__ ok,
                                                      __half* __restrict__ ov)
{
    extern __shared__ __align__(16) __half sm[];
    __half* Ah = sm;                     // [3][128*72]
    __half* Bh = sm + 3 * 128 * 72;      // [3][64*136]

    const int z = blockIdx.z;
    const float* bias = (z == 0) ? qb : (z == 1) ? kb : vb;
    __half* out = (z == 0) ? oq : (z == 1) ? ok : ov;
    const float osc = (z == 0) ? KS2 : 1.0f;
    const __half* Wz = Wh + (size_t)z * H_ * E_ * D_;

    const int m0   = blockIdx.x * 128;
    const int h0   = blockIdx.y * 2;
    const int tid  = threadIdx.x;
    const int lane = tid & 31;
    const int warp = tid >> 5;
    const int wm   = warp >> 2;
    const int wn   = warp & 3;
    const int g    = lane >> 2;
    const int tg   = lane & 3;

    const int ar = tid >> 3, ac = (tid & 7) * 8;
    const int br = tid >> 4, bc = tid & 15;

    auto issue = [&](int kt, int buf) {
        __half* Ad = Ah + buf * 128 * 72;
        #pragma unroll
        for (int j = 0; j < 4; j++) {
            int r = ar + j * 32;
            cpa16(Ad + (size_t)r * 72 + ac,
                  Xh + (size_t)(m0 + r) * E_ + kt * 64 + ac);
        }
        __half* Bd = Bh + buf * 64 * 136;
        #pragma unroll
        for (int j = 0; j < 4; j++) {
            int r = br + j * 16;
            int h = h0 + (bc >> 3);
            int d = (bc & 7) * 8;
            cpa16(Bd + (size_t)r * 136 + bc * 8,
                  Wz + ((size_t)h * E_ + kt * 64 + r) * D_ + d);
        }
    };

    issue(0, 0); CP_COMMIT();
    issue(1, 1); CP_COMMIT();
    CP_WAIT(1);
    __syncthreads();

    float acc[4][4][4] = {};

    for (int kt = 0; kt < 16; kt++) {
        const int buf = kt % 3;
        const __half* At = Ah + buf * 128 * 72;
        const __half* Bt = Bh + buf * 64 * 136;
        #pragma unroll
        for (int ks = 0; ks < 4; ks++) {
            uint32_t a[4][4], b[8];
            #pragma unroll
            for (int mf = 0; mf < 4; mf++)
                ldsmA16(a[mf], At, wm * 64 + mf * 16, ks * 16, lane, 72);
            ldsmBt16(&b[0], Bt, wn * 32 + 0,  ks * 16, lane, 136);
            ldsmBt16(&b[4], Bt, wn * 32 + 16, ks * 16, lane, 136);
            #pragma unroll
            for (int mf = 0; mf < 4; mf++)
                #pragma unroll
                for (int nf = 0; nf < 4; nf++)
                    mma16(acc[mf][nf], a[mf], &b[nf * 2]);
        }
        CP_WAIT(0);
        __syncthreads();
        if (kt + 2 < 16) { issue(kt + 2, (kt + 2) % 3); CP_COMMIT(); }
    }

    // epilogue
    #pragma unroll
    for (int mf = 0; mf < 4; mf++) {
        #pragma unroll
        for (int hh = 0; hh < 2; hh++) {
            int m  = m0 + wm * 64 + mf * 16 + g + hh * 8;
            int bb = m >> 11;
            int t  = m & (T_ - 1);
            #pragma unroll
            for (int nf = 0; nf < 4; nf++) {
                int nn = wn * 32 + nf * 8 + 2 * tg;
                int h  = h0 + (nn >> 6);
                int d  = nn & 63;
                float v0 = (acc[mf][nf][hh * 2 + 0] + bias[h * D_ + d]) * osc;
                float v1 = (acc[mf][nf][hh * 2 + 1] + bias[h * D_ + d + 1]) * osc;
                *reinterpret_cast<__half2*>(
                    out + (((size_t)bb * H_ + h) * T_ + t) * D_ + d) =
                    __floats2half2_rn(v0, v1);
            }
        }
    }
}

// ---------------------------------------------------------------------------
// Pass A: column softmax stats. Q pre-scaled (acc already log2-domain).
// Warp-local (m,z) + cross-warp merge. ONE barrier per t-tile.
// Emits lcs[s] = -m - log2(z).
// ---------------------------------------------------------------------------
__global__ __launch_bounds__(256) void stats_kernel(const __half* __restrict__ Q,
                                                    const __half* __restrict__ K,
                                                    float* __restrict__ cs_out)
{
    extern __shared__ __align__(16) __half sm[];
    __half* Ks = sm;                     // [128*72]
    __half* Qs = sm + 128 * 72;          // [3][128*72]
    float* redm = reinterpret_cast<float*>(sm + 4 * 128 * 72);   // [2][256]
    float* redz = redm + 512;                                    // [2][256]
    float* mrun = redz + 512;                                    // [128]
    float* zrun = mrun + 128;                                    // [128]

    const int st   = blockIdx.x;
    const int bh   = blockIdx.y;
    const int tid  = threadIdx.x;
    const int lane = tid & 31;
    const int warp = tid >> 5;
    const int wm   = warp >> 2;
    const int wn   = warp & 3;
    const int tg   = lane & 3;

    const int fr = tid >> 3, fc = (tid & 7) * 8;

    auto issueQ = [&](int it, int buf) {
        __half* Qd = Qs + buf * 128 * 72;
        const __half* Qp = Q + ((size_t)bh * T_ + it * 128) * D_;
        #pragma unroll
        for (int j = 0; j < 4; j++) {
            int r = fr + j * 32;
            cpa16(Qd + (size_t)r * 72 + fc, Qp + (size_t)r * D_ + fc);
        }
    };

    {
        const __half* Kp = K + ((size_t)bh * T_ + st * 128) * D_;
        #pragma unroll
        for (int j = 0; j < 4; j++) {
            int r = fr + j * 32;
            cpa16(Ks + (size_t)r * 72 + fc, Kp + (size_t)r * D_ + fc);
        }
        issueQ(st, st % 3);
        CP_COMMIT();
        int n1 = (st + 1 < 16) ? st + 1 : st;
        issueQ(n1, (st + 1) % 3);
        CP_COMMIT();
    }
    if (tid < 128) { mrun[tid] = -3.0e38f; zrun[tid] = 0.f; }
    CP_WAIT(1);
    __syncthreads();

    for (int it = st; it < 16; it++) {
        const __half* Qt = Qs + (it % 3) * 128 * 72;
        const int par = it & 1;

        float acc[4][4][4] = {};
        #pragma unroll
        for (int ks = 0; ks < 4; ks++) {
            uint32_t a[4][4], b[8];
            #pragma unroll
            for (int mf = 0; mf < 4; mf++)
                ldsmA16(a[mf], Qt, wm * 64 + mf * 16, ks * 16, lane, 72);
            ldsmBn16(&b[0], Ks, wn * 32 + 0,  ks * 16, lane, 72);
            ldsmBn16(&b[4], Ks, wn * 32 + 16, ks * 16, lane, 72);
            #pragma unroll
            for (int mf = 0; mf < 4; mf++)
                #pragma unroll
                for (int nf = 0; nf < 4; nf++)
                    mma16(acc[mf][nf], a[mf], &b[nf * 2]);
        }

        // causal mask (diag tile only; values already log2-domain)
        if (it == st) {
            #pragma unroll
            for (int mf = 0; mf < 4; mf++)
                #pragma unroll
                for (int hh = 0; hh < 2; hh++) {
                    int tl = wm * 64 + mf * 16 + (lane >> 2) + hh * 8;
                    #pragma unroll
                    for (int nf = 0; nf < 4; nf++)
                        #pragma unroll
                        for (int ci = 0; ci < 2; ci++) {
                            int sl = wn * 32 + nf * 8 + 2 * tg + ci;
                            if (tl < sl) acc[mf][nf][hh * 2 + ci] = -3.0e38f;
                        }
                }
        }

        // warp-local column max + exp-sum
        #pragma unroll
        for (int nf = 0; nf < 4; nf++)
            #pragma unroll
            for (int ci = 0; ci < 2; ci++) {
                float v = -3.0e38f;
                #pragma unroll
                for (int mf = 0; mf < 4; mf++) {
                    v = fmaxf(v, acc[mf][nf][ci]);
                    v = fmaxf(v, acc[mf][nf][2 + ci]);
                }
                v = fmaxf(v, __shfl_xor_sync(0xffffffffu, v, 4));
                v = fmaxf(v, __shfl_xor_sync(0xffffffffu, v, 8));
                v = fmaxf(v, __shfl_xor_sync(0xffffffffu, v, 16));
                float zs = 0.f;
                #pragma unroll
                for (int mf = 0; mf < 4; mf++) {
                    zs += fex2(acc[mf][nf][ci] - v);
                    zs += fex2(acc[mf][nf][2 + ci] - v);
                }
                zs += __shfl_xor_sync(0xffffffffu, zs, 4);
                zs += __shfl_xor_sync(0xffffffffu, zs, 8);
                zs += __shfl_xor_sync(0xffffffffu, zs, 16);
                if (lane < 4) {
                    int col = wn * 32 + nf * 8 + 2 * tg + ci;
                    redm[par * 256 + wm * 128 + col] = v;
                    redz[par * 256 + wm * 128 + col] = zs;
                }
            }

        CP_WAIT(0);
        __syncthreads();

        if (tid < 128) {
            float m0 = redm[par * 256 + tid],      m1 = redm[par * 256 + 128 + tid];
            float z0 = redz[par * 256 + tid],      z1 = redz[par * 256 + 128 + tid];
            float mt = fmaxf(m0, m1);
            float zt = z0 * fex2(m0 - mt) + z1 * fex2(m1 - mt);
            float mo = mrun[tid];
            float mn = fmaxf(mo, mt);
            zrun[tid] = zrun[tid] * fex2(mo - mn) + zt * fex2(mt - mn);
            mrun[tid] = mn;
        }
        if (it + 2 < 16) { issueQ(it + 2, (it + 2) % 3); CP_COMMIT(); }
    }

    if (tid < 128) {
        int s = st * 128 + tid;
        float l2z;
        asm("lg2.approx.f32 %0, %1;" : "=f"(l2z) : "f"(zrun[tid]));
        cs_out[bh * T_ + s] = -(mrun[tid] + l2z);   // lcs = -m - log2(z)
    }
}

// ---------------------------------------------------------------------------
// Pass B (FA2-style): out = P @ V, P register-resident.
// p = exp2(qk' + lcs[s]) via ONE ex2.approx.f16x2 per element pair.
// grid (t_tile=16 reversed, bh=32), block 256, 8 warps of 16t x 64s.
// Triple-buffered K/V, ONE barrier per chunk.
// ---------------------------------------------------------------------------
__global__ __launch_bounds__(256, 2) void out_kernel(const __half* __restrict__ Q,
                                                     const __half* __restrict__ K,
                                                     const __half* __restrict__ V,
                                                     const float* __restrict__ cs_g,
                                                     float* __restrict__ out)
{
    extern __shared__ __align__(16) __half sm[];
    __half* Qs  = sm;                          // [128*72]
    __half* Ksm = sm + 128 * 72;               // [3][64*72]
    __half* Vsm = Ksm + 3 * 64 * 72;           // [3][64*72]
    float*  cs  = reinterpret_cast<float*>(Vsm + 3 * 64 * 72);   // [3][64] lcs

    const int tt   = (T_ / 128 - 1) - blockIdx.x;
    const int bh   = blockIdx.y;
    const int bb   = bh >> 4;
    const int h    = bh & 15;
    const int tid  = threadIdx.x;
    const int lane = tid & 31;
    const int warp = tid >> 5;      // rows warp*16 .. warp*16+15
    const int g    = lane >> 2;
    const int tg   = lane & 3;

    const int t0  = tt * 128;
    const int nch = 2 * tt + 2;

    const int fr = tid >> 3, fc = (tid & 7) * 8;

    const __half* Kb = K + (size_t)bh * T_ * D_;
    const __half* Vb = V + (size_t)bh * T_ * D_;

    auto issueKV = [&](int ic, int buf) {
        const __half* Kp = Kb + (size_t)ic * 64 * D_;
        const __half* Vp = Vb + (size_t)ic * 64 * D_;
        __half* Kd = Ksm + buf * 64 * 72;
        __half* Vd = Vsm + buf * 64 * 72;
        #pragma unroll
        for (int j = 0; j < 2; j++) {
            int r = fr + j * 32;
            cpa16(Kd + (size_t)r * 72 + fc, Kp + (size_t)r * D_ + fc);
            cpa16(Vd + (size_t)r * 72 + fc, Vp + (size_t)r * D_ + fc);
        }
        if (tid < 64) cpa4(cs + buf * 64 + tid, cs_g + (size_t)bh * T_ + ic * 64 + tid);
    };

    // prologue: Q tile + chunk0 (group 0), chunk1 (group 1)
    {
        const __half* Qp = Q + ((size_t)bh * T_ + t0) * D_;
        #pragma unroll
        for (int j = 0; j < 4; j++) {
            int r = fr + j * 32;
            cpa16(Qs + (size_t)r * 72 + fc, Qp + (size_t)r * D_ + fc);
        }
        issueKV(0, 0); CP_COMMIT();
        issueKV(1, 1); CP_COMMIT();
    }
    CP_WAIT(1);          // Q + chunk0 done
    __syncthreads();

    // persistent Q fragments: 16 rows, full k=64 (4 k-groups)
    uint32_t aq[4][4];
    #pragma unroll
    for (int ks = 0; ks < 4; ks++)
        ldsmA16(aq[ks], Qs, warp * 16, ks * 16, lane, 72);

    float oacc[8][4] = {};

    for (int ic = 0; ic < nch; ic++) {
        CP_WAIT(1);          // chunk ic KV landed (newest pending = ic+1)
        __syncthreads();     // visibility + buffer-reuse protection
        if (ic + 2 < nch) { issueKV(ic + 2, (ic + 2) % 3); CP_COMMIT(); }

        const int s0  = ic * 64;
        const int b3  = ic % 3;
        const __half* Kt = Ksm + b3 * 64 * 72;
        const __half* Vt = Vsm + b3 * 64 * 72;
        const float*  cb = cs + b3 * 64;

        // QK: 16t x 64s, k=64 (Q frags persistent)
        float sacc[8][4] = {};
        #pragma unroll
        for (int ks = 0; ks < 4; ks++) {
            uint32_t bk[16];
            ldsmBn16(&bk[0],  Kt, 0,  ks * 16, lane, 72);
            ldsmBn16(&bk[4],  Kt, 16, ks * 16, lane, 72);
            ldsmBn16(&bk[8],  Kt, 32, ks * 16, lane, 72);
            ldsmBn16(&bk[12], Kt, 48, ks * 16, lane, 72);
            #pragma unroll
            for (int nf = 0; nf < 8; nf++)
                mma16(sacc[nf], aq[ks], &bk[nf * 2]);
        }

        // y = qk' + lcs[s]; mask; p = exp2(y) via f16x2 MUFU (2 elems/op);
        // result lands directly in PV A-fragment layout.
        const bool needmask = (s0 + 63 > t0);
        const int tl0 = t0 + warp * 16 + g;
        const int tl1 = tl0 + 8;
        uint32_t pa[4][4];
        #pragma unroll
        for (int nf = 0; nf < 8; nf++) {
            int sl = nf * 8 + 2 * tg;
            float y0 = sacc[nf][0] + cb[sl];
            float y1 = sacc[nf][1] + cb[sl + 1];
            float y2 = sacc[nf][2] + cb[sl];
            float y3 = sacc[nf][3] + cb[sl + 1];
            if (needmask) {
                int sa = s0 + sl;
                if (sa > tl0)     y0 = -1.0e4f;
                if (sa + 1 > tl0) y1 = -1.0e4f;
                if (sa > tl1)     y2 = -1.0e4f;
                if (sa + 1 > tl1) y3 = -1.0e4f;
            }
            int kg = nf >> 1;
            int hi = (nf & 1) * 2;
            pa[kg][hi + 0] = ex2x2(y0, y1);
            pa[kg][hi + 1] = ex2x2(y2, y3);
        }

        // PV: 16t x 64d, k=64 (P in registers)
        #pragma unroll
        for (int kg = 0; kg < 4; kg++) {
            uint32_t bv[16];
            ldsmBt16(&bv[0],  Vt, 0,  kg * 16, lane, 72);
            ldsmBt16(&bv[4],  Vt, 16, kg * 16, lane, 72);
            ldsmBt16(&bv[8],  Vt, 32, kg * 16, lane, 72);
            ldsmBt16(&bv[12], Vt, 48, kg * 16, lane, 72);
            #pragma unroll
            for (int nf = 0; nf < 8; nf++)
                mma16(oacc[nf], pa[kg], &bv[nf * 2]);
        }
    }

    // epilogue: (B,T,H,D) head-major concat
    #pragma unroll
    for (int hh = 0; hh < 2; hh++) {
        int t = t0 + warp * 16 + g + hh * 8;
        #pragma unroll
        for (int nf = 0; nf < 8; nf++) {
            int d = nf * 8 + 2 * tg;
            float2 val;
            val.x = oacc[nf][hh * 2 + 0];
            val.y = oacc[nf][hh * 2 + 1];
            *reinterpret_cast<float2*>(
                out + (((size_t)bb * T_ + t) * H_ + h) * D_ + d) = val;
        }
    }
}

// ---------------------------------------------------------------------------
// Launch
// ---------------------------------------------------------------------------
extern "C" void kernel_launch(void* const* d_in, const int* in_sizes, int n_in,
                              void* d_out, int out_size)
{
    const float* X   = (const float*)d_in[0];
    const float* k_w = (const float*)d_in[1];
    const float* k_b = (const float*)d_in[2];
    const float* q_w = (const float*)d_in[3];
    const float* q_b = (const float*)d_in[4];
    const float* v_w = (const float*)d_in[5];
    const float* v_b = (const float*)d_in[6];
    float* out = (float*)d_out;

    __half *pxh, *pwh, *pq, *pk, *pv;
    float* pcs;
    cudaGetSymbolAddress((void**)&pxh, g_xh);
    cudaGetSymbolAddress((void**)&pwh, g_wh);
    cudaGetSymbolAddress((void**)&pq, g_q);
    cudaGetSymbolAddress((void**)&pk, g_k);
    cudaGetSymbolAddress((void**)&pv, g_v);
    cudaGetSymbolAddress((void**)&pcs, g_cs);

    const int SP = 3 * (128 * 72 + 64 * 136) * 2;                         // 107520
    const int SA = 4 * 128 * 72 * 2 + (512 + 512 + 128 + 128) * 4;        // 78848
    const int SB = (128 * 72 + 6 * 64 * 72) * 2 + 3 * 64 * 4;             // 74496

    cudaFuncSetAttribute(proj_kernel,  cudaFuncAttributeMaxDynamicSharedMemorySize, SP);
    cudaFuncSetAttribute(stats_kernel, cudaFuncAttributeMaxDynamicSharedMemorySize, SA);
    cudaFuncSetAttribute(out_kernel,   cudaFuncAttributeMaxDynamicSharedMemorySize, SB);

    prep_kernel<<<7168, 256>>>(X, q_w, k_w, v_w, pxh, pwh);

    dim3 projGrid(B_ * T_ / 128, H_ / 2, 3);
    proj_kernel<<<projGrid, 256, SP>>>(pxh, pwh, q_b, k_b, v_b, pq, pk, pv);

    dim3 stGrid(T_ / 128, BH_);
    stats_kernel<<<stGrid, 256, SA>>>(pq, pk, pcs);

    dim3 outGrid(T_ / 128, BH_);
    out_kernel<<<outGrid, 256, SB>>>(pq, pk, pv, pcs, out);
}

// round 13
// speedup vs baseline: 2.8167x; 1.0297x over previous
#include <cuda_runtime.h>
#include <cuda_fp16.h>
#include <cstdint>

#define B_  2
#define T_  2048
#define E_  1024
#define H_  16
#define D_  64
#define BH_ (B_*H_)       // 32

// scale * log2(e): softmax computed in base-2 domain (folded into Q at proj)
#define KS2 0.18033688011112042592f

// ---------------------------------------------------------------------------
// Device scratch
// ---------------------------------------------------------------------------
__device__ __half g_xh[(size_t)B_ * T_ * E_];
__device__ __half g_wh[(size_t)3 * H_ * E_ * D_];
__device__ __half g_q[(size_t)BH_ * T_ * D_];      // pre-scaled by KS2
__device__ __half g_k[(size_t)BH_ * T_ * D_];
__device__ __half g_v[(size_t)BH_ * T_ * D_];      // scaled in-place by zinv in stats
__device__ float  g_mn[(size_t)BH_ * T_];          // -m (column max, log2 domain)

// ---------------------------------------------------------------------------
// helpers
// ---------------------------------------------------------------------------
__device__ __forceinline__ float fex2(float x) {
    float r;
    asm("ex2.approx.f32 %0, %1;" : "=f"(r) : "f"(x));
    return r;
}

// pack two fp32 -> half2, then 2^x on both halves in ONE MUFU op.
__device__ __forceinline__ uint32_t ex2x2(float lo, float hi) {
    uint32_t h, r;
    asm("cvt.rn.f16x2.f32 %0, %1, %2;" : "=r"(h) : "f"(hi), "f"(lo));
    asm("ex2.approx.f16x2 %0, %1;" : "=r"(r) : "r"(h));
    return r;
}

__device__ __forceinline__ void mma16(float* c, const uint32_t* a, const uint32_t* b) {
    asm("mma.sync.aligned.m16n8k16.row.col.f32.f16.f16.f32 "
        "{%0,%1,%2,%3},{%4,%5,%6,%7},{%8,%9},{%0,%1,%2,%3};"
        : "+f"(c[0]), "+f"(c[1]), "+f"(c[2]), "+f"(c[3])
        : "r"(a[0]), "r"(a[1]), "r"(a[2]), "r"(a[3]), "r"(b[0]), "r"(b[1]));
}

__device__ __forceinline__ void ldsmA16(uint32_t* r, const __half* base,
                                        int row0, int k0, int lane, int S) {
    const __half* p = base + (size_t)(row0 + (lane & 7) + ((lane >> 3) & 1) * 8) * S
                      + k0 + (lane >> 4) * 8;
    uint32_t a = (uint32_t)__cvta_generic_to_shared(p);
    asm volatile("ldmatrix.sync.aligned.m8n8.x4.shared.b16 {%0,%1,%2,%3}, [%4];"
                 : "=r"(r[0]), "=r"(r[1]), "=r"(r[2]), "=r"(r[3]) : "r"(a));
}

__device__ __forceinline__ void ldsmBn16(uint32_t* r, const __half* base,
                                         int n0, int k0, int lane, int S) {
    const __half* p = base + (size_t)(n0 + (lane & 7) + (lane >> 4) * 8) * S
                      + k0 + ((lane >> 3) & 1) * 8;
    uint32_t a = (uint32_t)__cvta_generic_to_shared(p);
    asm volatile("ldmatrix.sync.aligned.m8n8.x4.shared.b16 {%0,%1,%2,%3}, [%4];"
                 : "=r"(r[0]), "=r"(r[1]), "=r"(r[2]), "=r"(r[3]) : "r"(a));
}

__device__ __forceinline__ void ldsmBt16(uint32_t* r, const __half* base,
                                         int n0, int k0, int lane, int S) {
    const __half* p = base + (size_t)(k0 + (lane & 7) + ((lane >> 3) & 1) * 8) * S
                      + n0 + (lane >> 4) * 8;
    uint32_t a = (uint32_t)__cvta_generic_to_shared(p);
    asm volatile("ldmatrix.sync.aligned.m8n8.x4.trans.shared.b16 {%0,%1,%2,%3}, [%4];"
                 : "=r"(r[0]), "=r"(r[1]), "=r"(r[2]), "=r"(r[3]) : "r"(a));
}

__device__ __forceinline__ void cpa16(void* smem_ptr, const void* g) {
    uint32_t a = (uint32_t)__cvta_generic_to_shared(smem_ptr);
    asm volatile("cp.async.cg.shared.global [%0], [%1], 16;" :: "r"(a), "l"(g));
}
__device__ __forceinline__ void cpa4(void* smem_ptr, const void* g) {
    uint32_t a = (uint32_t)__cvta_generic_to_shared(smem_ptr);
    asm volatile("cp.async.ca.shared.global [%0], [%1], 4;" :: "r"(a), "l"(g));
}
#define CP_COMMIT() asm volatile("cp.async.commit_group;" ::: "memory")
#define CP_WAIT(N)  asm volatile("cp.async.wait_group " #N ";" ::: "memory")

// ---------------------------------------------------------------------------
// Kernel 0: convert X and W to fp16 scratch.
// ---------------------------------------------------------------------------
__global__ __launch_bounds__(256) void prep_kernel(const float* __restrict__ X,
                                                   const float* __restrict__ qw,
                                                   const float* __restrict__ kw,
                                                   const float* __restrict__ vw,
                                                   __half* __restrict__ Xh,
                                                   __half* __restrict__ Wh)
{
    const size_t XN4 = (size_t)B_ * T_ * E_ / 4;
    size_t i4 = (size_t)blockIdx.x * 256 + threadIdx.x;
    float4 v;
    uint2* dst;
    if (i4 < XN4) {
        v = reinterpret_cast<const float4*>(X)[i4];
        dst = reinterpret_cast<uint2*>(Xh) + i4;
    } else {
        size_t j = i4 - XN4;
        size_t base = j * 4;
        int z = (int)(base >> 20);
        size_t rem = base & ((1u << 20) - 1);
        const float* W = (z == 0) ? qw : (z == 1) ? kw : vw;
        v = *reinterpret_cast<const float4*>(W + rem);
        dst = reinterpret_cast<uint2*>(Wh) + j;
    }
    __half2 lo = __floats2half2_rn(v.x, v.y);
    __half2 hi = __floats2half2_rn(v.z, v.w);
    uint2 u;
    u.x = *reinterpret_cast<uint32_t*>(&lo);
    u.y = *reinterpret_cast<uint32_t*>(&hi);
    *dst = u;
}

// ---------------------------------------------------------------------------
// Kernel 1: fused QKV projection. 128m x 128n block, 8 warps of 64x32.
// Triple-buffered cp.async, ONE barrier per K-tile. Q output scaled by KS2.
// ---------------------------------------------------------------------------
__global__ __launch_bounds__(256, 2) void proj_kernel(const __half* __restrict__ Xh,
                                                      const __half* __restrict__ Wh,
                                                      const float* __restrict__ qb,
                                                      const float* __restrict__ kb,
                                                      const float* __restrict__ vb,
                                                      __half* __restrict__ oq,
                                                      __half* __restrict__ ok,
                                                      __half* __restrict__ ov)
{
    extern __shared__ __align__(16) __half sm[];
    __half* Ah = sm;                     // [3][128*72]
    __half* Bh = sm + 3 * 128 * 72;      // [3][64*136]

    const int z = blockIdx.z;
    const float* bias = (z == 0) ? qb : (z == 1) ? kb : vb;
    __half* out = (z == 0) ? oq : (z == 1) ? ok : ov;
    const float osc = (z == 0) ? KS2 : 1.0f;
    const __half* Wz = Wh + (size_t)z * H_ * E_ * D_;

    const int m0   = blockIdx.x * 128;
    const int h0   = blockIdx.y * 2;
    const int tid  = threadIdx.x;
    const int lane = tid & 31;
    const int warp = tid >> 5;
    const int wm   = warp >> 2;
    const int wn   = warp & 3;
    const int g    = lane >> 2;
    const int tg   = lane & 3;

    const int ar = tid >> 3, ac = (tid & 7) * 8;
    const int br = tid >> 4, bc = tid & 15;

    auto issue = [&](int kt, int buf) {
        __half* Ad = Ah + buf * 128 * 72;
        #pragma unroll
        for (int j = 0; j < 4; j++) {
            int r = ar + j * 32;
            cpa16(Ad + (size_t)r * 72 + ac,
                  Xh + (size_t)(m0 + r) * E_ + kt * 64 + ac);
        }
        __half* Bd = Bh + buf * 64 * 136;
        #pragma unroll
        for (int j = 0; j < 4; j++) {
            int r = br + j * 16;
            int h = h0 + (bc >> 3);
            int d = (bc & 7) * 8;
            cpa16(Bd + (size_t)r * 136 + bc * 8,
                  Wz + ((size_t)h * E_ + kt * 64 + r) * D_ + d);
        }
    };

    issue(0, 0); CP_COMMIT();
    issue(1, 1); CP_COMMIT();
    CP_WAIT(1);
    __syncthreads();

    float acc[4][4][4] = {};

    for (int kt = 0; kt < 16; kt++) {
        const int buf = kt % 3;
        const __half* At = Ah + buf * 128 * 72;
        const __half* Bt = Bh + buf * 64 * 136;
        #pragma unroll
        for (int ks = 0; ks < 4; ks++) {
            uint32_t a[4][4], b[8];
            #pragma unroll
            for (int mf = 0; mf < 4; mf++)
                ldsmA16(a[mf], At, wm * 64 + mf * 16, ks * 16, lane, 72);
            ldsmBt16(&b[0], Bt, wn * 32 + 0,  ks * 16, lane, 136);
            ldsmBt16(&b[4], Bt, wn * 32 + 16, ks * 16, lane, 136);
            #pragma unroll
            for (int mf = 0; mf < 4; mf++)
                #pragma unroll
                for (int nf = 0; nf < 4; nf++)
                    mma16(acc[mf][nf], a[mf], &b[nf * 2]);
        }
        CP_WAIT(0);
        __syncthreads();
        if (kt + 2 < 16) { issue(kt + 2, (kt + 2) % 3); CP_COMMIT(); }
    }

    // epilogue
    #pragma unroll
    for (int mf = 0; mf < 4; mf++) {
        #pragma unroll
        for (int hh = 0; hh < 2; hh++) {
            int m  = m0 + wm * 64 + mf * 16 + g + hh * 8;
            int bb = m >> 11;
            int t  = m & (T_ - 1);
            #pragma unroll
            for (int nf = 0; nf < 4; nf++) {
                int nn = wn * 32 + nf * 8 + 2 * tg;
                int h  = h0 + (nn >> 6);
                int d  = nn & 63;
                float v0 = (acc[mf][nf][hh * 2 + 0] + bias[h * D_ + d]) * osc;
                float v1 = (acc[mf][nf][hh * 2 + 1] + bias[h * D_ + d + 1]) * osc;
                *reinterpret_cast<__half2*>(
                    out + (((size_t)bb * H_ + h) * T_ + t) * D_ + d) =
                    __floats2half2_rn(v0, v1);
            }
        }
    }
}

// ---------------------------------------------------------------------------
// Pass A: column softmax stats. Emits mn[s] = -m and scales V rows by 1/z
// in-place. z-sums use f16x2 ex2 (terms vs warp-local max: |arg| small ->
// fp16-input rounding harmless), accumulated in fp32.
// ---------------------------------------------------------------------------
__global__ __launch_bounds__(256) void stats_kernel(const __half* __restrict__ Q,
                                                    const __half* __restrict__ K,
                                                    float* __restrict__ mn_out,
                                                    __half* __restrict__ Vv)
{
    extern __shared__ __align__(16) __half sm[];
    __half* Ks = sm;                     // [128*72]
    __half* Qs = sm + 128 * 72;          // [3][128*72]
    float* redm = reinterpret_cast<float*>(sm + 4 * 128 * 72);   // [2][256]
    float* redz = redm + 512;                                    // [2][256]
    float* mrun = redz + 512;                                    // [128]
    float* zrun = mrun + 128;                                    // [128]

    const int st   = blockIdx.x;
    const int bh   = blockIdx.y;
    const int tid  = threadIdx.x;
    const int lane = tid & 31;
    const int warp = tid >> 5;
    const int wm   = warp >> 2;
    const int wn   = warp & 3;
    const int tg   = lane & 3;

    const int fr = tid >> 3, fc = (tid & 7) * 8;

    auto issueQ = [&](int it, int buf) {
        __half* Qd = Qs + buf * 128 * 72;
        const __half* Qp = Q + ((size_t)bh * T_ + it * 128) * D_;
        #pragma unroll
        for (int j = 0; j < 4; j++) {
            int r = fr + j * 32;
            cpa16(Qd + (size_t)r * 72 + fc, Qp + (size_t)r * D_ + fc);
        }
    };

    {
        const __half* Kp = K + ((size_t)bh * T_ + st * 128) * D_;
        #pragma unroll
        for (int j = 0; j < 4; j++) {
            int r = fr + j * 32;
            cpa16(Ks + (size_t)r * 72 + fc, Kp + (size_t)r * D_ + fc);
        }
        issueQ(st, st % 3);
        CP_COMMIT();
        int n1 = (st + 1 < 16) ? st + 1 : st;
        issueQ(n1, (st + 1) % 3);
        CP_COMMIT();
    }
    if (tid < 128) { mrun[tid] = -3.0e38f; zrun[tid] = 0.f; }
    CP_WAIT(1);
    __syncthreads();

    for (int it = st; it < 16; it++) {
        const __half* Qt = Qs + (it % 3) * 128 * 72;
        const int par = it & 1;

        float acc[4][4][4] = {};
        #pragma unroll
        for (int ks = 0; ks < 4; ks++) {
            uint32_t a[4][4], b[8];
            #pragma unroll
            for (int mf = 0; mf < 4; mf++)
                ldsmA16(a[mf], Qt, wm * 64 + mf * 16, ks * 16, lane, 72);
            ldsmBn16(&b[0], Ks, wn * 32 + 0,  ks * 16, lane, 72);
            ldsmBn16(&b[4], Ks, wn * 32 + 16, ks * 16, lane, 72);
            #pragma unroll
            for (int mf = 0; mf < 4; mf++)
                #pragma unroll
                for (int nf = 0; nf < 4; nf++)
                    mma16(acc[mf][nf], a[mf], &b[nf * 2]);
        }

        // causal mask (diag tile only; values already log2-domain)
        if (it == st) {
            #pragma unroll
            for (int mf = 0; mf < 4; mf++)
                #pragma unroll
                for (int hh = 0; hh < 2; hh++) {
                    int tl = wm * 64 + mf * 16 + (lane >> 2) + hh * 8;
                    #pragma unroll
                    for (int nf = 0; nf < 4; nf++)
                        #pragma unroll
                        for (int ci = 0; ci < 2; ci++) {
                            int sl = wn * 32 + nf * 8 + 2 * tg + ci;
                            if (tl < sl) acc[mf][nf][hh * 2 + ci] = -3.0e38f;
                        }
                }
        }

        // warp-local column max (fp32) + exp-sum via f16x2, fp32 accumulate
        #pragma unroll
        for (int nf = 0; nf < 4; nf++) {
            float v0 = -3.0e38f, v1 = -3.0e38f;
            #pragma unroll
            for (int mf = 0; mf < 4; mf++) {
                v0 = fmaxf(v0, fmaxf(acc[mf][nf][0], acc[mf][nf][2]));
                v1 = fmaxf(v1, fmaxf(acc[mf][nf][1], acc[mf][nf][3]));
            }
            #pragma unroll
            for (int off = 4; off <= 16; off <<= 1) {
                v0 = fmaxf(v0, __shfl_xor_sync(0xffffffffu, v0, off));
                v1 = fmaxf(v1, __shfl_xor_sync(0xffffffffu, v1, off));
            }
            float zs0 = 0.f, zs1 = 0.f;
            #pragma unroll
            for (int mf = 0; mf < 4; mf++) {
                uint32_t e0 = ex2x2(acc[mf][nf][0] - v0, acc[mf][nf][1] - v1);
                uint32_t e1 = ex2x2(acc[mf][nf][2] - v0, acc[mf][nf][3] - v1);
                __half2 hs = __hadd2(*reinterpret_cast<__half2*>(&e0),
                                     *reinterpret_cast<__half2*>(&e1));
                float2 fs = __half22float2(hs);
                zs0 += fs.x;
                zs1 += fs.y;
            }
            #pragma unroll
            for (int off = 4; off <= 16; off <<= 1) {
                zs0 += __shfl_xor_sync(0xffffffffu, zs0, off);
                zs1 += __shfl_xor_sync(0xffffffffu, zs1, off);
            }
            if (lane < 4) {
                int col = wn * 32 + nf * 8 + 2 * tg;
                redm[par * 256 + wm * 128 + col]     = v0;
                redm[par * 256 + wm * 128 + col + 1] = v1;
                redz[par * 256 + wm * 128 + col]     = zs0;
                redz[par * 256 + wm * 128 + col + 1] = zs1;
            }
        }

        CP_WAIT(0);
        __syncthreads();

        if (tid < 128) {
            float m0 = redm[par * 256 + tid],      m1 = redm[par * 256 + 128 + tid];
            float z0 = redz[par * 256 + tid],      z1 = redz[par * 256 + 128 + tid];
            float mt = fmaxf(m0, m1);
            float zt = z0 * fex2(m0 - mt) + z1 * fex2(m1 - mt);
            float mo = mrun[tid];
            float mn = fmaxf(mo, mt);
            zrun[tid] = zrun[tid] * fex2(mo - mn) + zt * fex2(mt - mn);
            mrun[tid] = mn;
        }
        if (it + 2 < 16) { issueQ(it + 2, (it + 2) % 3); CP_COMMIT(); }
    }

    if (tid < 128) {
        int s = st * 128 + tid;
        mn_out[bh * T_ + s] = -mrun[tid];
        zrun[tid] = 1.0f / zrun[tid];
    }
    __syncthreads();

    // scale V rows [st*128, st*128+128) by zinv, in place (fp16)
    {
        int row = tid >> 1;
        int co  = (tid & 1) * 32;
        __half2 zh = __float2half2_rn(zrun[row]);
        __half* vp = Vv + ((size_t)bh * T_ + st * 128 + row) * D_ + co;
        #pragma unroll
        for (int j = 0; j < 4; j++) {
            uint4 u = *reinterpret_cast<uint4*>(vp + j * 8);
            __half2* hp = reinterpret_cast<__half2*>(&u);
            hp[0] = __hmul2(hp[0], zh);
            hp[1] = __hmul2(hp[1], zh);
            hp[2] = __hmul2(hp[2], zh);
            hp[3] = __hmul2(hp[3], zh);
            *reinterpret_cast<uint4*>(vp + j * 8) = u;
        }
    }
}

// ---------------------------------------------------------------------------
// Pass B (FA2-style): out = P @ V', P register-resident, V' pre-scaled by 1/z.
// p = exp2(qk' - m[s]) via ONE ex2.approx.f16x2 per element pair; exponent
// argument is small for significant elements -> fp16-input rounding safe.
// Masked chunks peeled out of the main loop.
// ---------------------------------------------------------------------------
__global__ __launch_bounds__(256, 2) void out_kernel(const __half* __restrict__ Q,
                                                     const __half* __restrict__ K,
                                                     const __half* __restrict__ V,
                                                     const float* __restrict__ mn_g,
                                                     float* __restrict__ out)
{
    extern __shared__ __align__(16) __half sm[];
    __half* Qs  = sm;                          // [128*72]
    __half* Ksm = sm + 128 * 72;               // [3][64*72]
    __half* Vsm = Ksm + 3 * 64 * 72;           // [3][64*72]
    float*  mn  = reinterpret_cast<float*>(Vsm + 3 * 64 * 72);   // [3][64] = -m

    const int tt   = (T_ / 128 - 1) - blockIdx.x;
    const int bh   = blockIdx.y;
    const int bb   = bh >> 4;
    const int h    = bh & 15;
    const int tid  = threadIdx.x;
    const int lane = tid & 31;
    const int warp = tid >> 5;      // rows warp*16 .. warp*16+15
    const int g    = lane >> 2;
    const int tg   = lane & 3;

    const int t0  = tt * 128;
    const int nch = 2 * tt + 2;

    const int fr = tid >> 3, fc = (tid & 7) * 8;

    const __half* Kb = K + (size_t)bh * T_ * D_;
    const __half* Vb = V + (size_t)bh * T_ * D_;

    auto issueKV = [&](int ic, int buf) {
        const __half* Kp = Kb + (size_t)ic * 64 * D_;
        const __half* Vp = Vb + (size_t)ic * 64 * D_;
        __half* Kd = Ksm + buf * 64 * 72;
        __half* Vd = Vsm + buf * 64 * 72;
        #pragma unroll
        for (int j = 0; j < 2; j++) {
            int r = fr + j * 32;
            cpa16(Kd + (size_t)r * 72 + fc, Kp + (size_t)r * D_ + fc);
            cpa16(Vd + (size_t)r * 72 + fc, Vp + (size_t)r * D_ + fc);
        }
        if (tid < 64) cpa4(mn + buf * 64 + tid, mn_g + (size_t)bh * T_ + ic * 64 + tid);
    };

    // prologue: Q tile + chunk0 (group 0), chunk1 (group 1)
    {
        const __half* Qp = Q + ((size_t)bh * T_ + t0) * D_;
        #pragma unroll
        for (int j = 0; j < 4; j++) {
            int r = fr + j * 32;
            cpa16(Qs + (size_t)r * 72 + fc, Qp + (size_t)r * D_ + fc);
        }
        issueKV(0, 0); CP_COMMIT();
        issueKV(1, 1); CP_COMMIT();
    }
    CP_WAIT(1);          // Q + chunk0 done
    __syncthreads();

    // persistent Q fragments: 16 rows, full k=64 (4 k-groups)
    uint32_t aq[4][4];
    #pragma unroll
    for (int ks = 0; ks < 4; ks++)
        ldsmA16(aq[ks], Qs, warp * 16, ks * 16, lane, 72);

    float oacc[8][4] = {};

    auto run_chunk = [&](int ic, bool nm, bool last) {
        if (last) { CP_WAIT(0); } else { CP_WAIT(1); }
        __syncthreads();
        if (ic + 2 < nch) { issueKV(ic + 2, (ic + 2) % 3); CP_COMMIT(); }

        const int s0  = ic * 64;
        const int b3  = ic % 3;
        const __half* Kt = Ksm + b3 * 64 * 72;
        const __half* Vt = Vsm + b3 * 64 * 72;
        const float*  cb = mn + b3 * 64;

        // QK: 16t x 64s, k=64 (Q frags persistent)
        float sacc[8][4] = {};
        #pragma unroll
        for (int ks = 0; ks < 4; ks++) {
            uint32_t bk[16];
            ldsmBn16(&bk[0],  Kt, 0,  ks * 16, lane, 72);
            ldsmBn16(&bk[4],  Kt, 16, ks * 16, lane, 72);
            ldsmBn16(&bk[8],  Kt, 32, ks * 16, lane, 72);
            ldsmBn16(&bk[12], Kt, 48, ks * 16, lane, 72);
            #pragma unroll
            for (int nf = 0; nf < 8; nf++)
                mma16(sacc[nf], aq[ks], &bk[nf * 2]);
        }

        // y = qk' - m[s]; (mask on peeled chunks only); p = exp2(y) via f16x2
        const int tl0 = t0 + warp * 16 + g;
        const int tl1 = tl0 + 8;
        uint32_t pa[4][4];
        #pragma unroll
        for (int nf = 0; nf < 8; nf++) {
            int sl = nf * 8 + 2 * tg;
            float y0 = sacc[nf][0] + cb[sl];
            float y1 = sacc[nf][1] + cb[sl + 1];
            float y2 = sacc[nf][2] + cb[sl];
            float y3 = sacc[nf][3] + cb[sl + 1];
            if (nm) {
                int sa = s0 + sl;
                if (sa > tl0)     y0 = -1.0e4f;
                if (sa + 1 > tl0) y1 = -1.0e4f;
                if (sa > tl1)     y2 = -1.0e4f;
                if (sa + 1 > tl1) y3 = -1.0e4f;
            }
            int kg = nf >> 1;
            int hi = (nf & 1) * 2;
            pa[kg][hi + 0] = ex2x2(y0, y1);
            pa[kg][hi + 1] = ex2x2(y2, y3);
        }

        // PV: 16t x 64d, k=64 (P in registers, V pre-scaled by zinv)
        #pragma unroll
        for (int kg = 0; kg < 4; kg++) {
            uint32_t bv[16];
            ldsmBt16(&bv[0],  Vt, 0,  kg * 16, lane, 72);
            ldsmBt16(&bv[4],  Vt, 16, kg * 16, lane, 72);
            ldsmBt16(&bv[8],  Vt, 32, kg * 16, lane, 72);
            ldsmBt16(&bv[12], Vt, 48, kg * 16, lane, 72);
            #pragma unroll
            for (int nf = 0; nf < 8; nf++)
                mma16(oacc[nf], pa[kg], &bv[nf * 2]);
        }
    };

    for (int ic = 0; ic < nch - 2; ic++) run_chunk(ic, false, false);
    run_chunk(nch - 2, true, false);
    run_chunk(nch - 1, true, true);

    // epilogue: (B,T,H,D) head-major concat
    #pragma unroll
    for (int hh = 0; hh < 2; hh++) {
        int t = t0 + warp * 16 + g + hh * 8;
        #pragma unroll
        for (int nf = 0; nf < 8; nf++) {
            int d = nf * 8 + 2 * tg;
            float2 val;
            val.x = oacc[nf][hh * 2 + 0];
            val.y = oacc[nf][hh * 2 + 1];
            *reinterpret_cast<float2*>(
                out + (((size_t)bb * T_ + t) * H_ + h) * D_ + d) = val;
        }
    }
}

// ---------------------------------------------------------------------------
// Launch
// ---------------------------------------------------------------------------
extern "C" void kernel_launch(void* const* d_in, const int* in_sizes, int n_in,
                              void* d_out, int out_size)
{
    const float* X   = (const float*)d_in[0];
    const float* k_w = (const float*)d_in[1];
    const float* k_b = (const float*)d_in[2];
    const float* q_w = (const float*)d_in[3];
    const float* q_b = (const float*)d_in[4];
    const float* v_w = (const float*)d_in[5];
    const float* v_b = (const float*)d_in[6];
    float* out = (float*)d_out;

    __half *pxh, *pwh, *pq, *pk, *pv;
    float* pmn;
    cudaGetSymbolAddress((void**)&pxh, g_xh);
    cudaGetSymbolAddress((void**)&pwh, g_wh);
    cudaGetSymbolAddress((void**)&pq, g_q);
    cudaGetSymbolAddress((void**)&pk, g_k);
    cudaGetSymbolAddress((void**)&pv, g_v);
    cudaGetSymbolAddress((void**)&pmn, g_mn);

    const int SP = 3 * (128 * 72 + 64 * 136) * 2;                         // 107520
    const int SA = 4 * 128 * 72 * 2 + (512 + 512 + 128 + 128) * 4;        // 78848
    const int SB = (128 * 72 + 6 * 64 * 72) * 2 + 3 * 64 * 4;             // 74496

    cudaFuncSetAttribute(proj_kernel,  cudaFuncAttributeMaxDynamicSharedMemorySize, SP);
    cudaFuncSetAttribute(stats_kernel, cudaFuncAttributeMaxDynamicSharedMemorySize, SA);
    cudaFuncSetAttribute(out_kernel,   cudaFuncAttributeMaxDynamicSharedMemorySize, SB);

    prep_kernel<<<7168, 256>>>(X, q_w, k_w, v_w, pxh, pwh);

    dim3 projGrid(B_ * T_ / 128, H_ / 2, 3);
    proj_kernel<<<projGrid, 256, SP>>>(pxh, pwh, q_b, k_b, v_b, pq, pk, pv);

    dim3 stGrid(T_ / 128, BH_);
    stats_kernel<<<stGrid, 256, SA>>>(pq, pk, pmn, pv);

    dim3 outGrid(T_ / 128, BH_);
    out_kernel<<<outGrid, 256, SB>>>(pq, pk, pv, pmn, out);
}